// round 10
// baseline (speedup 1.0000x reference)
#include <cuda_runtime.h>
#include <cuda_bf16.h>

// Problem constants
#define NB   32
#define NN   8400
#define NCLS 80
#define NCF  (NN * NCLS)       // 672000 scores per batch
#define TOPK 1024
#define CAP  8192
#define NDET 300
#define THRS 0.001f
#define IOUT 0.7f

#define CLO    0.96875f        // high-region lower bound (31/32, exact fp32)
#define CSCAL  8192.0f         // (s-CLO)*2^13 -> 256 coarse bins over hi region
#define NBINS  32768           // cold-path fine bins
#define HWORDS 16384           // fine bins packed as u16 pairs (64 KB)
#define HSLICES 16
#define CAPB   32768           // per-batch candidate buffer (expected ~21000)
#define CSTRIDE 256            // counter spacing (1 KB) -> distinct L2 partitions

// ---------------- scratch (device globals; no allocation allowed) ----------
__device__ int                 g_cnt[NB * CSTRIDE];       // zero-init
__device__ unsigned long long  g_cand[NB * CAPB];         // 8 MB

// coarse hi-region bin (valid only for s > CLO): monotonic in s, 0..255
__device__ __forceinline__ unsigned binhi(float s) {
    unsigned b = (unsigned)(__fmul_rn(__fsub_rn(s, CLO), CSCAL));
    return b > 255u ? 255u : b;
}
// full-range bin (cold path): 0 for masked scores, else monotonic
__device__ __forceinline__ unsigned binlo2(float s) {
    if (!(s > THRS)) return 0u;
    unsigned b = (unsigned)(s * 32768.0f);
    return b > (NBINS - 1) ? (NBINS - 1) : b;
}

// warp-aggregated candidate emit: one ATOMG per hit-group
__device__ __forceinline__ void emit4(float4 v, unsigned idxbase,
                                      unsigned long long* __restrict__ cand,
                                      int* __restrict__ cnt, unsigned lmask) {
    float c[4] = {v.x, v.y, v.z, v.w};
    #pragma unroll
    for (int q = 0; q < 4; q++) {
        bool h = (c[q] > CLO);
        unsigned m = __ballot_sync(0xffffffffu, h);
        if (m) {
            int ldr = __ffs(m) - 1;
            int base = 0;
            if ((threadIdx.x & 31) == ldr) base = atomicAdd(cnt, __popc(m));
            base = __shfl_sync(0xffffffffu, base, ldr);
            if (h) {
                int p = base + __popc(m & lmask);
                if (p < CAPB)
                    cand[p] = ((unsigned long long)__float_as_uint(c[q]) << 32)
                            | (unsigned long long)(~(idxbase + q));
            }
        }
    }
}

// ---------------- kernel 1: pure capture scan --------------------------------
// grid (HSLICES, NB), 1024 threads. slice = 10500 = 10 full strides + tail 260.
__global__ void __launch_bounds__(1024) k_scan(const float4* __restrict__ s4) {
    const int b = blockIdx.y, s = blockIdx.x, t = threadIdx.x;
    const int lane = t & 31;
    const unsigned lmask = (1u << lane) - 1u;
    const int perb4 = NCF / 4;                 // 168000
    const int slice = perb4 / HSLICES;         // 10500
    const float4* src = s4 + (size_t)b * perb4 + (size_t)s * slice;
    unsigned long long* cand = g_cand + (size_t)b * CAPB;
    int* cnt = &g_cnt[b * CSTRIDE];
    const unsigned flatbase = (unsigned)((s * slice + t) * 4);

    // 10 always-valid strides (10*1024 = 10240 <= 10500)
    #pragma unroll
    for (int g = 0; g < 10; g += 2) {
        float4 a0 = src[g * 1024 + t];
        float4 a1 = src[g * 1024 + 1024 + t];
        emit4(a0, flatbase + g * 4096,        cand, cnt, lmask);
        emit4(a1, flatbase + g * 4096 + 4096, cand, cnt, lmask);
    }
    // tail: elements 10240..10499 (260)
    float4 a2 = (t < slice - 10240) ? src[10240 + t] : make_float4(0.f, 0.f, 0.f, 0.f);
    emit4(a2, flatbase + 40960, cand, cnt, lmask);
}

// bitonic register step: element index i, phase k2, distance j (<32)
__device__ __forceinline__ unsigned long long bstep(
    unsigned long long v, int i, int k2, int j) {
    unsigned long long o = __shfl_xor_sync(0xffffffffu, v, j);
    bool keepmax = (((i & k2) == 0) == ((i & j) == 0));
    unsigned long long mx = v > o ? v : o;
    unsigned long long mn = v > o ? o : v;
    return keepmax ? mx : mn;
}

// ---------------- kernel 2: threshold + filter + sort + NMS + output --------
// key u64 = (float_bits << 32) | ~flat_idx, descending ->
// score desc, flat idx ascending on ties (matches lax.top_k stability).
// Cross-class IoU is exactly 0 (class offset gap), so global greedy ==
// independent per-class greedy in global-rank order. IoU ops identical to
// reference: offset coords, strict > 0.7, __f*_rn arithmetic.
__global__ void __launch_bounds__(1024) k_sortnms(const float4* __restrict__ boxes,
                                                  const float4* __restrict__ s4,
                                                  float* __restrict__ out) {
    extern __shared__ unsigned long long sm[];       // CAP u64 = 64 KB dynamic
    __shared__ int scnt;
    __shared__ int sT;
    __shared__ unsigned hco[256];
    __shared__ float4 sbox[TOPK];                    // 16 KB
    __shared__ float sy1[TOPK], sx1[TOPK], sy2[TOPK], sx2[TOPK], sa[TOPK];
    __shared__ float ssc[TOPK];
    __shared__ short scls[TOPK];
    __shared__ unsigned short wcount[NCLS * 32];
    __shared__ unsigned short wbase [NCLS * 32];
    __shared__ unsigned short ctot[NCLS];
    __shared__ unsigned short cstart[NCLS + 1];
    __shared__ unsigned short list[TOPK];
    __shared__ unsigned char  skept[TOPK];
    __shared__ unsigned kw[32];
    __shared__ int kpref[33];

    int b = blockIdx.x;
    int t = threadIdx.x;
    int warp = t >> 5, lane = t & 31;
    const int perb4 = NCF / 4;
    int rawcnt = g_cnt[b * CSTRIDE];

    if (t == 0) scnt = 0;
    if (t < 256) hco[t] = 0;
    __syncthreads();

    unsigned long long* cand = g_cand + (size_t)b * CAPB;

    if (rawcnt >= TOPK && rawcnt <= CAPB) {
        // ---- hot: histogram candidates -> T -> filter into smem ----
        for (int i = t; i < rawcnt; i += 1024) {
            float sv = __uint_as_float((unsigned)(cand[i] >> 32));
            atomicAdd(&hco[binhi(sv)], 1u);
        }
        __syncthreads();
        if (t == 0) {
            unsigned cum = 0; int sel = 0;
            for (int c = 255; c >= 0; c--) {
                cum += hco[c];
                if (cum >= TOPK) { sel = c; break; }
            }
            sT = sel;
        }
        __syncthreads();
        unsigned T = (unsigned)sT;
        #pragma unroll 4
        for (int i = t; i < rawcnt; i += 1024) {
            unsigned long long kk = cand[i];
            float sv = __uint_as_float((unsigned)(kk >> 32));
            if (binhi(sv) >= T) {
                int p = atomicAdd(&scnt, 1);
                if (p < CAP) sm[p] = kk;
            }
        }
    } else {
        // ---- cold: full-range fine histogram + collect (always correct) ----
        unsigned* sh = (unsigned*)sm;                // 64 KB = HWORDS u32
        for (int i = t; i < HWORDS; i += 1024) sh[i] = 0;
        __syncthreads();
        const float4* src = s4 + (size_t)b * perb4;
        for (int i = t; i < perb4; i += 1024) {
            float4 v = src[i];
            float comp[4] = {v.x, v.y, v.z, v.w};
            #pragma unroll
            for (int q = 0; q < 4; q++) {
                unsigned k = binlo2(comp[q]);
                atomicAdd(&sh[k >> 1], 1u << ((k & 1) * 16));
            }
        }
        __syncthreads();
        if (t < 256) {
            unsigned sum = 0;
            for (int k = 0; k < 64; k++) {
                unsigned m = sh[t * 64 + k];
                sum += (m & 0xFFFFu) + (m >> 16);
            }
            hco[t] = sum;
        }
        __syncthreads();
        if (t == 0) {
            unsigned h0 = sh[0] & 0xFFFFu;
            int sel = -1; unsigned cum = 0, cums = 0;
            for (int c = 255; c >= 0; c--) {
                unsigned cc = hco[c] - (c == 0 ? h0 : 0u);
                if (cum + cc >= TOPK) { sel = c; cums = cum; break; }
                cum += cc;
            }
            int T = 1;
            if (sel >= 0) {
                unsigned cum2 = cums;
                int lo = (sel == 0) ? 1 : 0;
                for (int fb = 127; fb >= lo; fb--) {
                    int bin = (sel << 7) + fb;
                    unsigned m = sh[bin >> 1];
                    unsigned cc = (bin & 1) ? (m >> 16) : (m & 0xFFFFu);
                    cum2 += cc;
                    if (cum2 >= TOPK) { T = bin; break; }
                }
            }
            sT = T;
        }
        __syncthreads();
        // collect into g_cand (overwrite), then copy to smem after hist done
        unsigned T = (unsigned)sT;
        for (int i = t; i < perb4; i += 1024) {
            float4 v = src[i];
            float comp[4] = {v.x, v.y, v.z, v.w};
            #pragma unroll
            for (int q = 0; q < 4; q++) {
                float sv = comp[q];
                if (binlo2(sv) >= T) {
                    int p = atomicAdd(&scnt, 1);
                    if (p < CAPB) {
                        unsigned idx = (unsigned)(i * 4 + q);
                        cand[p] = ((unsigned long long)__float_as_uint(sv) << 32)
                                | (unsigned long long)(~idx);
                    }
                }
            }
        }
        __syncthreads();                             // also fences global (block)
        int cc = scnt; if (cc > CAP) cc = CAP;
        for (int i = t; i < cc; i += 1024) sm[i] = cand[i];
        __syncthreads();
        if (t == 0) scnt = cc;
    }
    __syncthreads();
    int cnt = scnt; if (cnt > CAP) cnt = CAP;
    int n2 = 2048;
    while (n2 < cnt) n2 <<= 1;
    for (int i = t; i < n2; i += 1024) if (i >= cnt) sm[i] = 0ull;
    __syncthreads();

    // ---- bitonic sort ----
    if (n2 == 2048) {
        const int i1 = t, i2 = t + 1024;
        unsigned long long a = sm[i1], c = sm[i2];
        #pragma unroll
        for (int k2 = 2; k2 <= 32; k2 <<= 1)
            #pragma unroll
            for (int j = k2 >> 1; j >= 1; j >>= 1) {
                a = bstep(a, i1, k2, j);
                c = bstep(c, i2, k2, j);
            }
        sm[i1] = a; sm[i2] = c;
        __syncthreads();
        #pragma unroll
        for (int k2 = 64; k2 <= 2048; k2 <<= 1) {
            for (int j = k2 >> 1; j >= 32; j >>= 1) {
                #pragma unroll
                for (int e = 0; e < 2; e++) {
                    int i = t + e * 1024;
                    int ixj = i ^ j;
                    if (ixj > i) {
                        unsigned long long x = sm[i], y = sm[ixj];
                        bool desc = ((i & k2) == 0);
                        if (desc ? (x < y) : (x > y)) { sm[i] = y; sm[ixj] = x; }
                    }
                }
                __syncthreads();
            }
            a = sm[i1]; c = sm[i2];
            #pragma unroll
            for (int j = 16; j >= 1; j >>= 1) {
                a = bstep(a, i1, k2, j);
                c = bstep(c, i2, k2, j);
            }
            sm[i1] = a; sm[i2] = c;
            __syncthreads();
        }
    } else {
        for (int k2 = 2; k2 <= n2; k2 <<= 1) {
            for (int j = k2 >> 1; j > 0; j >>= 1) {
                for (int i = t; i < n2; i += 1024) {
                    int ixj = i ^ j;
                    if (ixj > i) {
                        unsigned long long x = sm[i], y = sm[ixj];
                        bool desc = ((i & k2) == 0);
                        if (desc ? (x < y) : (x > y)) { sm[i] = y; sm[ixj] = x; }
                    }
                }
                __syncthreads();
            }
        }
    }

    // ---- gather top-1024 boxes + build offset coords ----
    {
        unsigned long long kk = sm[t];
        unsigned keyhi = (unsigned)(kk >> 32);
        float4 bx = make_float4(0.f, 0.f, 0.f, 0.f);
        int cls = 0; float sc = 0.f;
        if (keyhi != 0) {
            unsigned idx = ~(unsigned)(kk & 0xFFFFFFFFull);
            int n = (int)(idx / NCLS);
            cls = (int)(idx % NCLS);
            sc = __uint_as_float(keyhi);
            bx = boxes[b * NN + n];
        }
        sbox[t] = bx; scls[t] = (short)cls; ssc[t] = sc;
        float off = (float)cls * 4096.0f;            // exact in fp32
        float y1 = __fadd_rn(bx.x, off);
        float x1 = __fadd_rn(bx.y, off);
        float y2 = __fadd_rn(bx.z, off);
        float x2 = __fadd_rn(bx.w, off);
        sy1[t] = y1; sx1[t] = x1; sy2[t] = y2; sx2[t] = x2;
        sa[t] = __fmul_rn(__fadd_rn(__fsub_rn(x2, x1), 1.0f),
                          __fadd_rn(__fsub_rn(y2, y1), 1.0f));
    }
    float sc = ssc[t];
    int c = scls[t];
    bool valid = (sc > THRS);
    unsigned bal = __ballot_sync(0xffffffff, valid);
    if (lane == 0) kw[warp] = bal;
    for (int i = t; i < NCLS * 32; i += 1024) wcount[i] = 0;
    skept[t] = 1;
    __syncthreads();

    // ---- stable per-class list build ----
    int cc2 = valid ? c : 0x7FFF;
    unsigned mm = __match_any_sync(0xffffffffu, cc2);
    int rank = __popc(mm & ((1u << lane) - 1u));
    int ldr = __ffs(mm) - 1;
    if (valid && lane == ldr) wcount[cc2 * 32 + warp] = (unsigned short)__popc(mm);
    __syncthreads();
    if (t < NCLS) {
        int run = 0;
        for (int w = 0; w < 32; w++) {
            int v = wcount[t * 32 + w];
            wbase[t * 32 + w] = (unsigned short)run;
            run += v;
        }
        ctot[t] = (unsigned short)run;
    }
    __syncthreads();
    if (t == 0) {
        int s = 0;
        for (int c2 = 0; c2 < NCLS; c2++) { cstart[c2] = (unsigned short)s; s += ctot[c2]; }
        cstart[NCLS] = (unsigned short)s;
    }
    __syncthreads();
    if (valid) list[cstart[cc2] + wbase[cc2 * 32 + warp] + rank] = (unsigned short)t;
    __syncthreads();

    // ---- per-class greedy (one warp per class, strided) ----
    for (int c2 = warp; c2 < NCLS; c2 += 32) {
        int m = ctot[c2];
        if (m < 2) continue;
        int base = cstart[c2];
        if (m <= 32) {
            int tj = 0; bool kept = false;
            float jy1 = 0, jx1 = 0, jy2 = 0, jx2 = 0, ja = 0;
            if (lane < m) {
                tj = list[base + lane];
                jy1 = sy1[tj]; jx1 = sx1[tj]; jy2 = sy2[tj]; jx2 = sx2[tj]; ja = sa[tj];
                kept = true;
            }
            for (int i = 0; i < m - 1; i++) {
                unsigned alive = __ballot_sync(0xffffffffu, kept);
                if (!((alive >> i) & 1u)) continue;
                int ti = list[base + i];
                float iy1 = sy1[ti], ix1 = sx1[ti], iy2 = sy2[ti], ix2 = sx2[ti], ia = sa[ti];
                if (lane > i && kept) {
                    float yy1 = fmaxf(iy1, jy1);
                    float xx1 = fmaxf(ix1, jx1);
                    float yy2 = fminf(iy2, jy2);
                    float xx2 = fminf(ix2, jx2);
                    float ww = fmaxf(0.0f, __fadd_rn(__fsub_rn(xx2, xx1), 1.0f));
                    float hh = fmaxf(0.0f, __fadd_rn(__fsub_rn(yy2, yy1), 1.0f));
                    float inter = __fmul_rn(ww, hh);
                    float iou = __fdiv_rn(inter, __fsub_rn(__fadd_rn(ia, ja), inter));
                    if (iou > IOUT) kept = false;
                }
            }
            if (lane < m && !kept) atomicAnd(&kw[tj >> 5], ~(1u << (tj & 31)));
        } else {
            for (int i = 0; i < m - 1; i++) {
                __syncwarp();
                if (!skept[base + i]) continue;
                int ti = list[base + i];
                float iy1 = sy1[ti], ix1 = sx1[ti], iy2 = sy2[ti], ix2 = sx2[ti], ia = sa[ti];
                for (int k = i + 1 + lane; k < m; k += 32) {
                    if (skept[base + k]) {
                        int tk = list[base + k];
                        float yy1 = fmaxf(iy1, sy1[tk]);
                        float xx1 = fmaxf(ix1, sx1[tk]);
                        float yy2 = fminf(iy2, sy2[tk]);
                        float xx2 = fminf(ix2, sx2[tk]);
                        float ww = fmaxf(0.0f, __fadd_rn(__fsub_rn(xx2, xx1), 1.0f));
                        float hh = fmaxf(0.0f, __fadd_rn(__fsub_rn(yy2, yy1), 1.0f));
                        float inter = __fmul_rn(ww, hh);
                        float iou = __fdiv_rn(inter, __fsub_rn(__fadd_rn(ia, sa[tk]), inter));
                        if (iou > IOUT) skept[base + k] = 0;
                    }
                }
            }
            __syncwarp();
            for (int k = lane; k < m; k += 32)
                if (!skept[base + k]) {
                    int tk = list[base + k];
                    atomicAnd(&kw[tk >> 5], ~(1u << (tk & 31)));
                }
        }
    }
    __syncthreads();

    // ---- ranking + output ----
    if (t < 32) {
        unsigned my = kw[t];
        int p = __popc(my);
        int x = p;
        #pragma unroll
        for (int o = 1; o < 32; o <<= 1) {
            int y = __shfl_up_sync(0xffffffff, x, o);
            if (t >= o) x += y;
        }
        kpref[t] = x - p;
        if (t == 31) kpref[32] = x;
    }
    __syncthreads();

    int w = t >> 5, l = t & 31;
    unsigned kwv = kw[w];
    bool kept = (kwv >> l) & 1u;
    unsigned lowm = (l == 0) ? 0u : ((1u << l) - 1u);
    int TKall = kpref[32];

    int slot = -1;
    float oscore = 0.0f;
    if (kept) {
        int kr = kpref[w] + __popc(kwv & lowm);
        if (kr < NDET) { slot = kr; oscore = sc; }
    } else {
        int sr = (w << 5) - kpref[w] + __popc((~kwv) & lowm);
        int s2 = TKall + sr;
        if (s2 < NDET) { slot = s2; oscore = 0.0f; }
    }

    // output layout (float32): boxes[32,300,4] | scores[32,300] | labels[32,300] | n_valid[32,1]
    if (slot >= 0) {
        float4 bx = sbox[t];
        float* ob = out + ((size_t)b * NDET + slot) * 4;
        ob[0] = bx.x; ob[1] = bx.y; ob[2] = bx.z; ob[3] = bx.w;
        out[NB * NDET * 4 + b * NDET + slot] = oscore;
        out[NB * NDET * 5 + b * NDET + slot] = (float)c;
    }
    if (t == 0) {
        out[NB * NDET * 6 + b] = (float)(TKall < NDET ? TKall : NDET);
        g_cnt[b * CSTRIDE] = 0;                      // reset for next replay
    }
}

// ---------------- launch ----------------------------------------------------
extern "C" void kernel_launch(void* const* d_in, const int* in_sizes, int n_in,
                              void* d_out, int out_size) {
    const float* boxes  = (const float*)d_in[0];
    const float* scores = (const float*)d_in[1];
    if (n_in >= 2 && in_sizes[0] > in_sizes[1]) {
        boxes  = (const float*)d_in[1];
        scores = (const float*)d_in[0];
    }
    float* out = (float*)d_out;

    cudaFuncSetAttribute(k_sortnms, cudaFuncAttributeMaxDynamicSharedMemorySize, CAP * 8);

    k_scan   <<<dim3(HSLICES, NB), 1024>>>((const float4*)scores);
    k_sortnms<<<NB, 1024, CAP * 8>>>((const float4*)boxes, (const float4*)scores, out);
}

// round 11
// speedup vs baseline: 1.2959x; 1.2959x over previous
#include <cuda_runtime.h>
#include <cuda_bf16.h>

// Problem constants
#define NB   32
#define NN   8400
#define NCLS 80
#define NCF  (NN * NCLS)       // 672000 scores per batch
#define TOPK 1024
#define CAP  8192
#define NDET 300
#define THRS 0.001f
#define IOUT 0.7f

#define CLO    0.96875f        // high-region lower bound (31/32, exact fp32)
#define CSCAL  8192.0f         // (s-CLO)*2^13 -> 256 coarse bins over hi region
#define NBINS  32768           // cold-path fine bins
#define HWORDS 16384           // fine bins packed as u16 pairs (64 KB)
#define HSLICES 16
#define SEGCAP 128             // per-warp staging (expected ~41 hits)
#define CAPB   32768           // per-batch candidate buffer (expected ~21000)
#define CSTRIDE 256            // counter spacing (1 KB)

// ---------------- scratch (device globals; no allocation allowed) ----------
__device__ int                 g_cnt[NB * CSTRIDE];       // [b][0]=count, [b][1]=ovf
__device__ unsigned int        g_coarse[NB * 256];        // zero-init; self-reset
__device__ __align__(16) unsigned long long g_cand[NB * CAPB];  // 8 MB

// coarse hi-region bin (valid only for s > CLO): monotonic in s, 0..255
__device__ __forceinline__ unsigned binhi(float s) {
    unsigned b = (unsigned)(__fmul_rn(__fsub_rn(s, CLO), CSCAL));
    return b > 255u ? 255u : b;
}
// full-range bin (cold path): 0 for masked scores, else monotonic
__device__ __forceinline__ unsigned binlo2(float s) {
    if (!(s > THRS)) return 0u;
    unsigned b = (unsigned)(s * 32768.0f);
    return b > (NBINS - 1) ? (NBINS - 1) : b;
}

// ---------------- kernel 1: ballot-free scan + coarse hist ------------------
// grid (HSLICES, NB), 1024 threads, 33 KB smem (2 blocks/SM).
__global__ void __launch_bounds__(1024) k_scan(const float4* __restrict__ s4) {
    __shared__ unsigned long long stage[32 * SEGCAP];   // 32 KB
    __shared__ unsigned shc[256];
    __shared__ int wctr[32];
    __shared__ int woff[32];
    __shared__ int bbase;
    const int b = blockIdx.y, s = blockIdx.x, t = threadIdx.x;
    const int warp = t >> 5, lane = t & 31;
    if (t < 256) shc[t] = 0;
    if (t < 32) wctr[t] = 0;
    __syncthreads();

    const int perb4 = NCF / 4;                 // 168000
    const int slice = perb4 / HSLICES;         // 10500
    const float4* src = s4 + (size_t)b * perb4 + (size_t)s * slice;
    const unsigned idx0 = (unsigned)((s * slice + t) * 4);
    unsigned long long* mystage = stage + warp * SEGCAP;

    // 10 always-valid strides (10*1024 = 10240 <= 10500)
    #pragma unroll
    for (int g = 0; g < 10; g++) {
        float4 a = src[g * 1024 + t];
        float mx = fmaxf(fmaxf(a.x, a.y), fmaxf(a.z, a.w));
        if (mx > CLO) {
            float c[4] = {a.x, a.y, a.z, a.w};
            #pragma unroll
            for (int q = 0; q < 4; q++) {
                if (c[q] > CLO) {
                    atomicAdd(&shc[binhi(c[q])], 1u);
                    int p = atomicAdd(&wctr[warp], 1);
                    if (p < SEGCAP)
                        mystage[p] = ((unsigned long long)__float_as_uint(c[q]) << 32)
                                   | (unsigned long long)(~(idx0 + g * 4096u + q));
                }
            }
        }
    }
    // tail: elements 10240..10499 (260 float4)
    if (t < slice - 10240) {
        float4 a = src[10240 + t];
        float mx = fmaxf(fmaxf(a.x, a.y), fmaxf(a.z, a.w));
        if (mx > CLO) {
            float c[4] = {a.x, a.y, a.z, a.w};
            #pragma unroll
            for (int q = 0; q < 4; q++) {
                if (c[q] > CLO) {
                    atomicAdd(&shc[binhi(c[q])], 1u);
                    int p = atomicAdd(&wctr[warp], 1);
                    if (p < SEGCAP)
                        mystage[p] = ((unsigned long long)__float_as_uint(c[q]) << 32)
                                   | (unsigned long long)(~(idx0 + 40960u + q));
                }
            }
        }
    }
    __syncthreads();

    if (t == 0) {
        int run = 0;
        #pragma unroll
        for (int w = 0; w < 32; w++) {
            woff[w] = run;
            int n = wctr[w];
            run += (n > SEGCAP ? SEGCAP : n);
        }
        bbase = atomicAdd(&g_cnt[b * CSTRIDE], run);
    }
    if (t < 32 && wctr[t] > SEGCAP) g_cnt[b * CSTRIDE + 1] = 1;   // ovf flag
    __syncthreads();

    // flush warp segments (compacted) to global
    int n = wctr[warp]; if (n > SEGCAP) n = SEGCAP;
    unsigned long long* dst = g_cand + (size_t)b * CAPB + bbase + woff[warp];
    for (int off = lane; off < n; off += 32) dst[off] = mystage[off];
    // merge coarse histogram
    if (t < 256 && shc[t]) atomicAdd(&g_coarse[b * 256 + t], shc[t]);
}

// bitonic register step: element index i, phase k2, distance j (<32)
__device__ __forceinline__ unsigned long long bstep(
    unsigned long long v, int i, int k2, int j) {
    unsigned long long o = __shfl_xor_sync(0xffffffffu, v, j);
    bool keepmax = (((i & k2) == 0) == ((i & j) == 0));
    unsigned long long mx = v > o ? v : o;
    unsigned long long mn = v > o ? o : v;
    return keepmax ? mx : mn;
}

// ---------------- kernel 2: threshold + filter + sort + NMS + output --------
// key u64 = (float_bits << 32) | ~flat_idx, descending ->
// score desc, flat idx ascending on ties (matches lax.top_k stability).
// Cross-class IoU is exactly 0 (class offset gap), so global greedy ==
// independent per-class greedy in global-rank order. IoU ops identical to
// reference: offset coords, strict > 0.7, __f*_rn arithmetic.
__global__ void __launch_bounds__(1024) k_sortnms(const float4* __restrict__ boxes,
                                                  const float4* __restrict__ s4,
                                                  float* __restrict__ out) {
    extern __shared__ unsigned long long sm[];       // CAP u64 = 64 KB dynamic
    __shared__ int scnt;
    __shared__ int sT;
    __shared__ unsigned sbins[256];
    __shared__ float4 sbox[TOPK];                    // 16 KB
    __shared__ float sy1[TOPK], sx1[TOPK], sy2[TOPK], sx2[TOPK], sa[TOPK];
    __shared__ float ssc[TOPK];
    __shared__ short scls[TOPK];
    __shared__ unsigned short wcount[NCLS * 32];
    __shared__ unsigned short wbase [NCLS * 32];
    __shared__ unsigned short ctot[NCLS];
    __shared__ unsigned short cstart[NCLS + 1];
    __shared__ unsigned short list[TOPK];
    __shared__ unsigned char  skept[TOPK];
    __shared__ unsigned kw[32];
    __shared__ int kpref[33];

    int b = blockIdx.x;
    int t = threadIdx.x;
    int warp = t >> 5, lane = t & 31;
    const int perb4 = NCF / 4;
    int rawcnt = g_cnt[b * CSTRIDE];
    int ovf    = g_cnt[b * CSTRIDE + 1];

    if (t == 0) scnt = 0;
    if (t < 256) sbins[t] = g_coarse[b * 256 + t];
    __syncthreads();

    unsigned long long* cand = g_cand + (size_t)b * CAPB;
    bool hot = (rawcnt >= TOPK && rawcnt <= CAPB && !ovf);

    if (hot) {
        // ---- parallel suffix-sum threshold over 256 coarse bins ----
        for (int d = 1; d < 256; d <<= 1) {
            unsigned v = 0;
            if (t < 256) v = sbins[t] + ((t + d < 256) ? sbins[t + d] : 0u);
            __syncthreads();
            if (t < 256) sbins[t] = v;
            __syncthreads();
        }
        if (t < 256) {
            bool ok  = sbins[t] >= TOPK;
            bool nxt = (t == 255) ? false : (sbins[t + 1] >= TOPK);
            if (ok && !nxt) sT = t;
        }
        __syncthreads();
        // ---- single filter pass (2 keys per 16B load) ----
        unsigned T = (unsigned)sT;
        const ulonglong2* c2 = (const ulonglong2*)cand;
        int half = rawcnt >> 1;
        #pragma unroll 4
        for (int i = t; i < half; i += 1024) {
            ulonglong2 kk = c2[i];
            float s0 = __uint_as_float((unsigned)(kk.x >> 32));
            float s1 = __uint_as_float((unsigned)(kk.y >> 32));
            if (binhi(s0) >= T) { int p = atomicAdd(&scnt, 1); if (p < CAP) sm[p] = kk.x; }
            if (binhi(s1) >= T) { int p = atomicAdd(&scnt, 1); if (p < CAP) sm[p] = kk.y; }
        }
        if (t == 0 && (rawcnt & 1)) {
            unsigned long long kk = cand[rawcnt - 1];
            float sv = __uint_as_float((unsigned)(kk >> 32));
            if (binhi(sv) >= T) { int p = atomicAdd(&scnt, 1); if (p < CAP) sm[p] = kk; }
        }
    } else {
        // ---- cold: full-range fine histogram + collect (always correct) ----
        unsigned* sh = (unsigned*)sm;                // 64 KB = HWORDS u32
        for (int i = t; i < HWORDS; i += 1024) sh[i] = 0;
        __syncthreads();
        const float4* src = s4 + (size_t)b * perb4;
        for (int i = t; i < perb4; i += 1024) {
            float4 v = src[i];
            float comp[4] = {v.x, v.y, v.z, v.w};
            #pragma unroll
            for (int q = 0; q < 4; q++) {
                unsigned k = binlo2(comp[q]);
                atomicAdd(&sh[k >> 1], 1u << ((k & 1) * 16));
            }
        }
        __syncthreads();
        if (t < 256) {
            unsigned sum = 0;
            for (int k = 0; k < 64; k++) {
                unsigned m = sh[t * 64 + k];
                sum += (m & 0xFFFFu) + (m >> 16);
            }
            sbins[t] = sum;
        }
        __syncthreads();
        if (t == 0) {
            unsigned h0 = sh[0] & 0xFFFFu;
            int sel = -1; unsigned cum = 0, cums = 0;
            for (int c = 255; c >= 0; c--) {
                unsigned cc = sbins[c] - (c == 0 ? h0 : 0u);
                if (cum + cc >= TOPK) { sel = c; cums = cum; break; }
                cum += cc;
            }
            int T = 1;
            if (sel >= 0) {
                unsigned cum2 = cums;
                int lo = (sel == 0) ? 1 : 0;
                for (int fb = 127; fb >= lo; fb--) {
                    int bin = (sel << 7) + fb;
                    unsigned m = sh[bin >> 1];
                    unsigned cc = (bin & 1) ? (m >> 16) : (m & 0xFFFFu);
                    cum2 += cc;
                    if (cum2 >= TOPK) { T = bin; break; }
                }
            }
            sT = T;
        }
        __syncthreads();
        unsigned T = (unsigned)sT;
        for (int i = t; i < perb4; i += 1024) {
            float4 v = src[i];
            float comp[4] = {v.x, v.y, v.z, v.w};
            #pragma unroll
            for (int q = 0; q < 4; q++) {
                float sv = comp[q];
                if (binlo2(sv) >= T) {
                    int p = atomicAdd(&scnt, 1);
                    if (p < CAPB) {
                        unsigned idx = (unsigned)(i * 4 + q);
                        cand[p] = ((unsigned long long)__float_as_uint(sv) << 32)
                                | (unsigned long long)(~idx);
                    }
                }
            }
        }
        __syncthreads();
        int cc = scnt; if (cc > CAP) cc = CAP;
        for (int i = t; i < cc; i += 1024) sm[i] = cand[i];
        __syncthreads();
        if (t == 0) scnt = cc;
    }
    __syncthreads();
    int cnt = scnt; if (cnt > CAP) cnt = CAP;
    int n2 = 2048;
    while (n2 < cnt) n2 <<= 1;
    for (int i = t; i < n2; i += 1024) if (i >= cnt) sm[i] = 0ull;
    __syncthreads();

    // ---- bitonic sort ----
    if (n2 == 2048) {
        const int i1 = t, i2 = t + 1024;
        unsigned long long a = sm[i1], c = sm[i2];
        #pragma unroll
        for (int k2 = 2; k2 <= 32; k2 <<= 1)
            #pragma unroll
            for (int j = k2 >> 1; j >= 1; j >>= 1) {
                a = bstep(a, i1, k2, j);
                c = bstep(c, i2, k2, j);
            }
        sm[i1] = a; sm[i2] = c;
        __syncthreads();
        #pragma unroll
        for (int k2 = 64; k2 <= 2048; k2 <<= 1) {
            for (int j = k2 >> 1; j >= 32; j >>= 1) {
                #pragma unroll
                for (int e = 0; e < 2; e++) {
                    int i = t + e * 1024;
                    int ixj = i ^ j;
                    if (ixj > i) {
                        unsigned long long x = sm[i], y = sm[ixj];
                        bool desc = ((i & k2) == 0);
                        if (desc ? (x < y) : (x > y)) { sm[i] = y; sm[ixj] = x; }
                    }
                }
                __syncthreads();
            }
            a = sm[i1]; c = sm[i2];
            #pragma unroll
            for (int j = 16; j >= 1; j >>= 1) {
                a = bstep(a, i1, k2, j);
                c = bstep(c, i2, k2, j);
            }
            sm[i1] = a; sm[i2] = c;
            __syncthreads();
        }
    } else {
        for (int k2 = 2; k2 <= n2; k2 <<= 1) {
            for (int j = k2 >> 1; j > 0; j >>= 1) {
                for (int i = t; i < n2; i += 1024) {
                    int ixj = i ^ j;
                    if (ixj > i) {
                        unsigned long long x = sm[i], y = sm[ixj];
                        bool desc = ((i & k2) == 0);
                        if (desc ? (x < y) : (x > y)) { sm[i] = y; sm[ixj] = x; }
                    }
                }
                __syncthreads();
            }
        }
    }

    // ---- gather top-1024 boxes + build offset coords ----
    {
        unsigned long long kk = sm[t];
        unsigned keyhi = (unsigned)(kk >> 32);
        float4 bx = make_float4(0.f, 0.f, 0.f, 0.f);
        int cls = 0; float sc = 0.f;
        if (keyhi != 0) {
            unsigned idx = ~(unsigned)(kk & 0xFFFFFFFFull);
            int n = (int)(idx / NCLS);
            cls = (int)(idx % NCLS);
            sc = __uint_as_float(keyhi);
            bx = boxes[b * NN + n];
        }
        sbox[t] = bx; scls[t] = (short)cls; ssc[t] = sc;
        float off = (float)cls * 4096.0f;            // exact in fp32
        float y1 = __fadd_rn(bx.x, off);
        float x1 = __fadd_rn(bx.y, off);
        float y2 = __fadd_rn(bx.z, off);
        float x2 = __fadd_rn(bx.w, off);
        sy1[t] = y1; sx1[t] = x1; sy2[t] = y2; sx2[t] = x2;
        sa[t] = __fmul_rn(__fadd_rn(__fsub_rn(x2, x1), 1.0f),
                          __fadd_rn(__fsub_rn(y2, y1), 1.0f));
    }
    float sc = ssc[t];
    int c = scls[t];
    bool valid = (sc > THRS);
    unsigned bal = __ballot_sync(0xffffffff, valid);
    if (lane == 0) kw[warp] = bal;
    for (int i = t; i < NCLS * 32; i += 1024) wcount[i] = 0;
    skept[t] = 1;
    __syncthreads();

    // ---- stable per-class list build ----
    int cc2 = valid ? c : 0x7FFF;
    unsigned mm = __match_any_sync(0xffffffffu, cc2);
    int rank = __popc(mm & ((1u << lane) - 1u));
    int ldr = __ffs(mm) - 1;
    if (valid && lane == ldr) wcount[cc2 * 32 + warp] = (unsigned short)__popc(mm);
    __syncthreads();
    if (t < NCLS) {
        int run = 0;
        for (int w = 0; w < 32; w++) {
            int v = wcount[t * 32 + w];
            wbase[t * 32 + w] = (unsigned short)run;
            run += v;
        }
        ctot[t] = (unsigned short)run;
    }
    __syncthreads();
    if (t == 0) {
        int s = 0;
        for (int c2 = 0; c2 < NCLS; c2++) { cstart[c2] = (unsigned short)s; s += ctot[c2]; }
        cstart[NCLS] = (unsigned short)s;
    }
    __syncthreads();
    if (valid) list[cstart[cc2] + wbase[cc2 * 32 + warp] + rank] = (unsigned short)t;
    __syncthreads();

    // ---- per-class greedy (one warp per class, strided) ----
    for (int c2 = warp; c2 < NCLS; c2 += 32) {
        int m = ctot[c2];
        if (m < 2) continue;
        int base = cstart[c2];
        if (m <= 32) {
            int tj = 0; bool kept = false;
            float jy1 = 0, jx1 = 0, jy2 = 0, jx2 = 0, ja = 0;
            if (lane < m) {
                tj = list[base + lane];
                jy1 = sy1[tj]; jx1 = sx1[tj]; jy2 = sy2[tj]; jx2 = sx2[tj]; ja = sa[tj];
                kept = true;
            }
            for (int i = 0; i < m - 1; i++) {
                unsigned alive = __ballot_sync(0xffffffffu, kept);
                if (!((alive >> i) & 1u)) continue;
                int ti = list[base + i];
                float iy1 = sy1[ti], ix1 = sx1[ti], iy2 = sy2[ti], ix2 = sx2[ti], ia = sa[ti];
                if (lane > i && kept) {
                    float yy1 = fmaxf(iy1, jy1);
                    float xx1 = fmaxf(ix1, jx1);
                    float yy2 = fminf(iy2, jy2);
                    float xx2 = fminf(ix2, jx2);
                    float ww = fmaxf(0.0f, __fadd_rn(__fsub_rn(xx2, xx1), 1.0f));
                    float hh = fmaxf(0.0f, __fadd_rn(__fsub_rn(yy2, yy1), 1.0f));
                    float inter = __fmul_rn(ww, hh);
                    float iou = __fdiv_rn(inter, __fsub_rn(__fadd_rn(ia, ja), inter));
                    if (iou > IOUT) kept = false;
                }
            }
            if (lane < m && !kept) atomicAnd(&kw[tj >> 5], ~(1u << (tj & 31)));
        } else {
            for (int i = 0; i < m - 1; i++) {
                __syncwarp();
                if (!skept[base + i]) continue;
                int ti = list[base + i];
                float iy1 = sy1[ti], ix1 = sx1[ti], iy2 = sy2[ti], ix2 = sx2[ti], ia = sa[ti];
                for (int k = i + 1 + lane; k < m; k += 32) {
                    if (skept[base + k]) {
                        int tk = list[base + k];
                        float yy1 = fmaxf(iy1, sy1[tk]);
                        float xx1 = fmaxf(ix1, sx1[tk]);
                        float yy2 = fminf(iy2, sy2[tk]);
                        float xx2 = fminf(ix2, sx2[tk]);
                        float ww = fmaxf(0.0f, __fadd_rn(__fsub_rn(xx2, xx1), 1.0f));
                        float hh = fmaxf(0.0f, __fadd_rn(__fsub_rn(yy2, yy1), 1.0f));
                        float inter = __fmul_rn(ww, hh);
                        float iou = __fdiv_rn(inter, __fsub_rn(__fadd_rn(ia, sa[tk]), inter));
                        if (iou > IOUT) skept[base + k] = 0;
                    }
                }
            }
            __syncwarp();
            for (int k = lane; k < m; k += 32)
                if (!skept[base + k]) {
                    int tk = list[base + k];
                    atomicAnd(&kw[tk >> 5], ~(1u << (tk & 31)));
                }
        }
    }
    __syncthreads();

    // ---- ranking + output ----
    if (t < 32) {
        unsigned my = kw[t];
        int p = __popc(my);
        int x = p;
        #pragma unroll
        for (int o = 1; o < 32; o <<= 1) {
            int y = __shfl_up_sync(0xffffffff, x, o);
            if (t >= o) x += y;
        }
        kpref[t] = x - p;
        if (t == 31) kpref[32] = x;
    }
    __syncthreads();

    int w = t >> 5, l = t & 31;
    unsigned kwv = kw[w];
    bool kept = (kwv >> l) & 1u;
    unsigned lowm = (l == 0) ? 0u : ((1u << l) - 1u);
    int TKall = kpref[32];

    int slot = -1;
    float oscore = 0.0f;
    if (kept) {
        int kr = kpref[w] + __popc(kwv & lowm);
        if (kr < NDET) { slot = kr; oscore = sc; }
    } else {
        int sr = (w << 5) - kpref[w] + __popc((~kwv) & lowm);
        int s2 = TKall + sr;
        if (s2 < NDET) { slot = s2; oscore = 0.0f; }
    }

    // output layout (float32): boxes[32,300,4] | scores[32,300] | labels[32,300] | n_valid[32,1]
    if (slot >= 0) {
        float4 bx = sbox[t];
        float* ob = out + ((size_t)b * NDET + slot) * 4;
        ob[0] = bx.x; ob[1] = bx.y; ob[2] = bx.z; ob[3] = bx.w;
        out[NB * NDET * 4 + b * NDET + slot] = oscore;
        out[NB * NDET * 5 + b * NDET + slot] = (float)c;
    }
    // reset per-replay state
    if (t < 256) g_coarse[b * 256 + t] = 0;
    if (t == 0) {
        out[NB * NDET * 6 + b] = (float)(TKall < NDET ? TKall : NDET);
        g_cnt[b * CSTRIDE] = 0;
        g_cnt[b * CSTRIDE + 1] = 0;
    }
}

// ---------------- launch ----------------------------------------------------
extern "C" void kernel_launch(void* const* d_in, const int* in_sizes, int n_in,
                              void* d_out, int out_size) {
    const float* boxes  = (const float*)d_in[0];
    const float* scores = (const float*)d_in[1];
    if (n_in >= 2 && in_sizes[0] > in_sizes[1]) {
        boxes  = (const float*)d_in[1];
        scores = (const float*)d_in[0];
    }
    float* out = (float*)d_out;

    cudaFuncSetAttribute(k_sortnms, cudaFuncAttributeMaxDynamicSharedMemorySize, CAP * 8);

    k_scan   <<<dim3(HSLICES, NB), 1024>>>((const float4*)scores);
    k_sortnms<<<NB, 1024, CAP * 8>>>((const float4*)boxes, (const float4*)scores, out);
}

// round 12
// speedup vs baseline: 1.3546x; 1.0452x over previous
#include <cuda_runtime.h>
#include <cuda_bf16.h>

// Problem constants
#define NB   32
#define NN   8400
#define NCLS 80
#define NCF  (NN * NCLS)       // 672000 scores per batch
#define TOPK 1024
#define CAP  8192
#define NDET 300
#define THRS 0.001f
#define IOUT 0.7f

#define CLO    0.96875f        // high-region lower bound (31/32, exact fp32)
#define NBINS  32768           // cold-path fine bins
#define HWORDS 16384           // fine bins packed as u16 pairs (64 KB)
#define HSLICES 16
#define SEGCAP 128             // per-warp staging (expected ~41 hits)
#define CAPB   32768           // per-batch candidate buffer (expected ~21000)
#define CSTRIDE 256            // counter spacing (1 KB)
#define SIDECAP 512
#define SIDE2CAP 32

// ---------------- scratch (device globals; no allocation allowed) ----------
__device__ int                 g_cnt[NB * CSTRIDE];       // [b][0]=count, [b][1]=ovf
__device__ unsigned int        g_coarse[NB * 256];        // zero-init; self-reset
__device__ __align__(16) unsigned long long g_cand[NB * CAPB];  // 8 MB

// 21-bit hi-region value: (s-CLO) is exact (Sterbenz), *2^21 exact (pow2).
__device__ __forceinline__ unsigned v21(float s) {
    unsigned v = (unsigned)(__fmul_rn(__fsub_rn(s, CLO), 2097152.0f));
    return v > 65535u ? 65535u : v;
}
__device__ __forceinline__ unsigned binhi(float s)  { return v21(s) >> 8; }   // 0..255
__device__ __forceinline__ unsigned sub8(float s)   { return v21(s) & 255u; } // 0..255
// full-range bin (cold path): 0 for masked scores, else monotonic
__device__ __forceinline__ unsigned binlo2(float s) {
    if (!(s > THRS)) return 0u;
    unsigned b = (unsigned)(s * 32768.0f);
    return b > (NBINS - 1) ? (NBINS - 1) : b;
}

// ---------------- kernel 1: ballot-free scan + coarse hist ------------------
// grid (HSLICES, NB), 1024 threads, 33 KB smem (2 blocks/SM). (unchanged R11)
__global__ void __launch_bounds__(1024) k_scan(const float4* __restrict__ s4) {
    __shared__ unsigned long long stage[32 * SEGCAP];   // 32 KB
    __shared__ unsigned shc[256];
    __shared__ int wctr[32];
    __shared__ int woff[32];
    __shared__ int bbase;
    const int b = blockIdx.y, s = blockIdx.x, t = threadIdx.x;
    const int warp = t >> 5, lane = t & 31;
    if (t < 256) shc[t] = 0;
    if (t < 32) wctr[t] = 0;
    __syncthreads();

    const int perb4 = NCF / 4;                 // 168000
    const int slice = perb4 / HSLICES;         // 10500
    const float4* src = s4 + (size_t)b * perb4 + (size_t)s * slice;
    const unsigned idx0 = (unsigned)((s * slice + t) * 4);
    unsigned long long* mystage = stage + warp * SEGCAP;

    #pragma unroll
    for (int g = 0; g < 10; g++) {
        float4 a = src[g * 1024 + t];
        float mx = fmaxf(fmaxf(a.x, a.y), fmaxf(a.z, a.w));
        if (mx > CLO) {
            float c[4] = {a.x, a.y, a.z, a.w};
            #pragma unroll
            for (int q = 0; q < 4; q++) {
                if (c[q] > CLO) {
                    atomicAdd(&shc[binhi(c[q])], 1u);
                    int p = atomicAdd(&wctr[warp], 1);
                    if (p < SEGCAP)
                        mystage[p] = ((unsigned long long)__float_as_uint(c[q]) << 32)
                                   | (unsigned long long)(~(idx0 + g * 4096u + q));
                }
            }
        }
    }
    if (t < slice - 10240) {
        float4 a = src[10240 + t];
        float mx = fmaxf(fmaxf(a.x, a.y), fmaxf(a.z, a.w));
        if (mx > CLO) {
            float c[4] = {a.x, a.y, a.z, a.w};
            #pragma unroll
            for (int q = 0; q < 4; q++) {
                if (c[q] > CLO) {
                    atomicAdd(&shc[binhi(c[q])], 1u);
                    int p = atomicAdd(&wctr[warp], 1);
                    if (p < SEGCAP)
                        mystage[p] = ((unsigned long long)__float_as_uint(c[q]) << 32)
                                   | (unsigned long long)(~(idx0 + 40960u + q));
                }
            }
        }
    }
    __syncthreads();

    if (t == 0) {
        int run = 0;
        #pragma unroll
        for (int w = 0; w < 32; w++) {
            woff[w] = run;
            int n = wctr[w];
            run += (n > SEGCAP ? SEGCAP : n);
        }
        bbase = atomicAdd(&g_cnt[b * CSTRIDE], run);
    }
    if (t < 32 && wctr[t] > SEGCAP) g_cnt[b * CSTRIDE + 1] = 1;
    __syncthreads();

    int n = wctr[warp]; if (n > SEGCAP) n = SEGCAP;
    unsigned long long* dst = g_cand + (size_t)b * CAPB + bbase + woff[warp];
    for (int off = lane; off < n; off += 32) dst[off] = mystage[off];
    if (t < 256 && shc[t]) atomicAdd(&g_coarse[b * 256 + t], shc[t]);
}

// bitonic register step: element index i, phase k2, distance j (<32)
__device__ __forceinline__ unsigned long long bstep(
    unsigned long long v, int i, int k2, int j) {
    unsigned long long o = __shfl_xor_sync(0xffffffffu, v, j);
    bool keepmax = (((i & k2) == 0) == ((i & j) == 0));
    unsigned long long mx = v > o ? v : o;
    unsigned long long mn = v > o ? o : v;
    return keepmax ? mx : mn;
}

// warp suffix-pick over 256 bins: returns largest bin `sel` with
// suffix(sel) >= target, plus suffix(sel) and bins[sel]. One warp, all lanes.
__device__ __forceinline__ void warp_pick(const unsigned* bins, unsigned target,
                                          int lane, int& sel, unsigned& suf,
                                          unsigned& binv) {
    unsigned v[8], s[8];
    #pragma unroll
    for (int k = 0; k < 8; k++) v[k] = bins[lane * 8 + k];
    unsigned run = 0;
    #pragma unroll
    for (int k = 7; k >= 0; k--) { run += v[k]; s[k] = run; }
    unsigned acc = run;
    #pragma unroll
    for (int off = 1; off < 32; off <<= 1) {
        unsigned y = __shfl_down_sync(0xffffffffu, acc, off);
        if (lane + off < 32) acc += y;
    }
    unsigned above = acc - run;                    // groups strictly above mine
    int bestK = -1;
    #pragma unroll
    for (int k = 0; k < 8; k++) if (s[k] + above >= target) bestK = k;
    unsigned m = __ballot_sync(0xffffffffu, bestK >= 0);
    int selLane = 31 - __clz((int)m);
    unsigned mySuf = (bestK >= 0) ? s[bestK] + above : 0u;
    unsigned myBin = (bestK >= 0) ? v[bestK] : 0u;
    int selK = __shfl_sync(0xffffffffu, bestK, selLane);
    sel  = (selLane << 3) + selK;
    suf  = __shfl_sync(0xffffffffu, mySuf, selLane);
    binv = __shfl_sync(0xffffffffu, myBin, selLane);
}

// ---------------- kernel 2: exact-select + sort + per-class NMS + output ----
// key u64 = (float_bits << 32) | ~flat_idx, descending ->
// score desc, flat idx ascending on ties (matches lax.top_k stability).
// Cross-class IoU is exactly 0 (class offset gap), so global greedy ==
// independent per-class greedy in global-rank order. IoU ops identical to
// reference: offset coords, strict > 0.7, __f*_rn arithmetic.
__global__ void __launch_bounds__(1024) k_sortnms(const float4* __restrict__ boxes,
                                                  const float4* __restrict__ s4,
                                                  float* __restrict__ out) {
    extern __shared__ unsigned long long sm[];       // CAP u64 = 64 KB dynamic
    __shared__ int scnt, sflag, sT, sNeed, sidecnt, s2cnt;
    __shared__ unsigned hist2[256];
    __shared__ unsigned long long side[SIDECAP];     // 4 KB
    __shared__ unsigned long long side2[SIDE2CAP];
    __shared__ float4 sbox[TOPK];                    // 16 KB
    __shared__ float sy1[TOPK], sx1[TOPK], sy2[TOPK], sx2[TOPK], sa[TOPK];
    __shared__ float ssc[TOPK];
    __shared__ short scls[TOPK];
    __shared__ unsigned short wcount[NCLS * 32];
    __shared__ unsigned short wbase [NCLS * 32];
    __shared__ unsigned short ctot[NCLS];
    __shared__ unsigned short cstart[NCLS];
    __shared__ unsigned short list[TOPK];
    __shared__ unsigned char  skept[TOPK];
    __shared__ unsigned kw[32];
    __shared__ int kpref[33];

    int b = blockIdx.x;
    int t = threadIdx.x;
    int warp = t >> 5, lane = t & 31;
    const int perb4 = NCF / 4;
    int rawcnt = g_cnt[b * CSTRIDE];
    int ovf    = g_cnt[b * CSTRIDE + 1];

    if (t == 0) { scnt = 0; sflag = 0; sidecnt = 0; s2cnt = 0; }
    __syncthreads();

    unsigned long long* cand = g_cand + (size_t)b * CAPB;
    bool hot = (rawcnt >= TOPK && rawcnt <= CAPB && !ovf);
    bool fast = false;

    if (hot) {
        // ---- warp-0 suffix pick over coarse bins -> T, need ----
        if (warp == 0) {
            int T; unsigned suf, binv;
            warp_pick(&g_coarse[b * 256], TOPK, lane, T, suf, binv);
            if (lane == 0) { sT = T; sNeed = (int)(TOPK - (suf - binv)); }
        }
        __syncthreads();
        const int T = sT;
        // ---- filter: bin>T -> main, bin==T -> side ----
        {
            const ulonglong2* c2p = (const ulonglong2*)cand;
            int half = rawcnt >> 1;
            #pragma unroll 4
            for (int i = t; i < half; i += 1024) {
                ulonglong2 kk = c2p[i];
                #pragma unroll
                for (int e = 0; e < 2; e++) {
                    unsigned long long k = e ? kk.y : kk.x;
                    int bi = (int)binhi(__uint_as_float((unsigned)(k >> 32)));
                    if (bi > T) {
                        int p = atomicAdd(&scnt, 1);
                        if (p < TOPK) sm[p] = k; else sflag = 1;
                    } else if (bi == T) {
                        int p = atomicAdd(&sidecnt, 1);
                        if (p < SIDECAP) side[p] = k; else sflag = 1;
                    }
                }
            }
            if (t == 0 && (rawcnt & 1)) {
                unsigned long long k = cand[rawcnt - 1];
                int bi = (int)binhi(__uint_as_float((unsigned)(k >> 32)));
                if (bi > T) {
                    int p = atomicAdd(&scnt, 1);
                    if (p < TOPK) sm[p] = k; else sflag = 1;
                } else if (bi == T) {
                    int p = atomicAdd(&sidecnt, 1);
                    if (p < SIDECAP) side[p] = k; else sflag = 1;
                }
            }
        }
        __syncthreads();
        // ---- warp-0 side refinement: pick exactly `need` from bin T ----
        if (warp == 0 && !sflag) {
            int need = sNeed;
            int scn = sidecnt; if (scn > SIDECAP) scn = SIDECAP;
            if (need >= scn) {
                for (int i = lane; i < scn; i += 32) {
                    int p = atomicAdd(&scnt, 1);
                    if (p < TOPK) sm[p] = side[i];
                }
            } else {
                #pragma unroll
                for (int k = 0; k < 8; k++) hist2[lane * 8 + k] = 0;
                __syncwarp();
                for (int i = lane; i < scn; i += 32)
                    atomicAdd(&hist2[sub8(__uint_as_float((unsigned)(side[i] >> 32)))], 1u);
                __syncwarp();
                int T2; unsigned suf2, bin2;
                warp_pick(hist2, (unsigned)need, lane, T2, suf2, bin2);
                int need2 = need - (int)(suf2 - bin2);
                for (int i = lane; i < scn; i += 32) {
                    int sb = (int)sub8(__uint_as_float((unsigned)(side[i] >> 32)));
                    if (sb > T2) {
                        int p = atomicAdd(&scnt, 1);
                        if (p < TOPK) sm[p] = side[i];
                    } else if (sb == T2) {
                        int q = atomicAdd(&s2cnt, 1);
                        if (q < SIDE2CAP) side2[q] = side[i];
                    }
                }
                __syncwarp();
                int n2s = s2cnt;
                if (n2s > SIDE2CAP) { if (lane == 0) sflag = 1; }
                else if (lane < n2s) {
                    unsigned long long mk = side2[lane];
                    int r = 0;
                    for (int j = 0; j < n2s; j++) if (side2[j] > mk) r++;
                    if (r < need2) {
                        int p = atomicAdd(&scnt, 1);
                        if (p < TOPK) sm[p] = mk;
                    }
                }
            }
        }
        __syncthreads();
        if (t == 0 && scnt != TOPK) sflag = 1;      // exactness check
        __syncthreads();
        if (!sflag) {
            fast = true;
        } else {
            // generic refill: everything with bin >= T
            if (t == 0) scnt = 0;
            __syncthreads();
            for (int i = t; i < rawcnt; i += 1024) {
                unsigned long long k = cand[i];
                if ((int)binhi(__uint_as_float((unsigned)(k >> 32))) >= T) {
                    int p = atomicAdd(&scnt, 1);
                    if (p < CAP) sm[p] = k;
                }
            }
            __syncthreads();
        }
    } else {
        // ---- cold: full-range fine histogram + collect (always correct) ----
        unsigned* sh = (unsigned*)sm;                // 64 KB = HWORDS u32
        for (int i = t; i < HWORDS; i += 1024) sh[i] = 0;
        __syncthreads();
        const float4* src = s4 + (size_t)b * perb4;
        for (int i = t; i < perb4; i += 1024) {
            float4 v = src[i];
            float comp[4] = {v.x, v.y, v.z, v.w};
            #pragma unroll
            for (int q = 0; q < 4; q++) {
                unsigned k = binlo2(comp[q]);
                atomicAdd(&sh[k >> 1], 1u << ((k & 1) * 16));
            }
        }
        __syncthreads();
        if (t < 256) {
            unsigned sum = 0;
            for (int k = 0; k < 64; k++) {
                unsigned m = sh[t * 64 + k];
                sum += (m & 0xFFFFu) + (m >> 16);
            }
            hist2[t] = sum;
        }
        __syncthreads();
        if (t == 0) {
            unsigned h0 = sh[0] & 0xFFFFu;
            int sel = -1; unsigned cum = 0, cums = 0;
            for (int c = 255; c >= 0; c--) {
                unsigned cc = hist2[c] - (c == 0 ? h0 : 0u);
                if (cum + cc >= TOPK) { sel = c; cums = cum; break; }
                cum += cc;
            }
            int T = 1;
            if (sel >= 0) {
                unsigned cum2 = cums;
                int lo = (sel == 0) ? 1 : 0;
                for (int fb = 127; fb >= lo; fb--) {
                    int bin = (sel << 7) + fb;
                    unsigned m = sh[bin >> 1];
                    unsigned cc = (bin & 1) ? (m >> 16) : (m & 0xFFFFu);
                    cum2 += cc;
                    if (cum2 >= TOPK) { T = bin; break; }
                }
            }
            sT = T;
        }
        __syncthreads();
        unsigned T = (unsigned)sT;
        for (int i = t; i < perb4; i += 1024) {
            float4 v = src[i];
            float comp[4] = {v.x, v.y, v.z, v.w};
            #pragma unroll
            for (int q = 0; q < 4; q++) {
                float sv = comp[q];
                if (binlo2(sv) >= T) {
                    int p = atomicAdd(&scnt, 1);
                    if (p < CAPB) {
                        unsigned idx = (unsigned)(i * 4 + q);
                        cand[p] = ((unsigned long long)__float_as_uint(sv) << 32)
                                | (unsigned long long)(~idx);
                    }
                }
            }
        }
        __syncthreads();
        int cc = scnt; if (cc > CAP) cc = CAP;
        for (int i = t; i < cc; i += 1024) sm[i] = cand[i];
        __syncthreads();
        if (t == 0) scnt = cc;
        __syncthreads();
    }

    // ---- sort ----
    if (fast) {
        // n = 1024, 1 element/thread, hybrid bitonic
        __syncthreads();
        unsigned long long a = sm[t];
        #pragma unroll
        for (int k2 = 2; k2 <= 32; k2 <<= 1)
            #pragma unroll
            for (int j = k2 >> 1; j >= 1; j >>= 1)
                a = bstep(a, t, k2, j);
        sm[t] = a;
        __syncthreads();
        #pragma unroll
        for (int k2 = 64; k2 <= 1024; k2 <<= 1) {
            for (int j = k2 >> 1; j >= 32; j >>= 1) {
                int ixj = t ^ j;
                if (ixj > t) {
                    unsigned long long x = sm[t], y = sm[ixj];
                    bool desc = ((t & k2) == 0);
                    if (desc ? (x < y) : (x > y)) { sm[t] = y; sm[ixj] = x; }
                }
                __syncthreads();
            }
            a = sm[t];
            #pragma unroll
            for (int j = 16; j >= 1; j >>= 1) a = bstep(a, t, k2, j);
            sm[t] = a;
            __syncthreads();
        }
    } else {
        int cnt = scnt; if (cnt > CAP) cnt = CAP;
        int n2 = 2048;
        while (n2 < cnt) n2 <<= 1;
        for (int i = t; i < n2; i += 1024) if (i >= cnt) sm[i] = 0ull;
        __syncthreads();
        for (int k2 = 2; k2 <= n2; k2 <<= 1) {
            for (int j = k2 >> 1; j > 0; j >>= 1) {
                for (int i = t; i < n2; i += 1024) {
                    int ixj = i ^ j;
                    if (ixj > i) {
                        unsigned long long x = sm[i], y = sm[ixj];
                        bool desc = ((i & k2) == 0);
                        if (desc ? (x < y) : (x > y)) { sm[i] = y; sm[ixj] = x; }
                    }
                }
                __syncthreads();
            }
        }
    }

    // ---- gather top-1024 boxes + build offset coords ----
    {
        unsigned long long kk = sm[t];
        unsigned keyhi = (unsigned)(kk >> 32);
        float4 bx = make_float4(0.f, 0.f, 0.f, 0.f);
        int cls = 0; float sc = 0.f;
        if (keyhi != 0) {
            unsigned idx = ~(unsigned)(kk & 0xFFFFFFFFull);
            int n = (int)(idx / NCLS);
            cls = (int)(idx % NCLS);
            sc = __uint_as_float(keyhi);
            bx = boxes[b * NN + n];
        }
        sbox[t] = bx; scls[t] = (short)cls; ssc[t] = sc;
        float off = (float)cls * 4096.0f;            // exact in fp32
        float y1 = __fadd_rn(bx.x, off);
        float x1 = __fadd_rn(bx.y, off);
        float y2 = __fadd_rn(bx.z, off);
        float x2 = __fadd_rn(bx.w, off);
        sy1[t] = y1; sx1[t] = x1; sy2[t] = y2; sx2[t] = x2;
        sa[t] = __fmul_rn(__fadd_rn(__fsub_rn(x2, x1), 1.0f),
                          __fadd_rn(__fsub_rn(y2, y1), 1.0f));
    }
    float sc = ssc[t];
    int c = scls[t];
    bool valid = (sc > THRS);
    unsigned bal = __ballot_sync(0xffffffff, valid);
    if (lane == 0) kw[warp] = bal;
    for (int i = t; i < NCLS * 32; i += 1024) wcount[i] = 0;
    skept[t] = 1;
    __syncthreads();

    // ---- stable per-class list build (parallel scans) ----
    int cc2 = valid ? c : 0x7FFF;
    unsigned mm = __match_any_sync(0xffffffffu, cc2);
    int rank = __popc(mm & ((1u << lane) - 1u));
    int ldr = __ffs(mm) - 1;
    if (valid && lane == ldr) wcount[cc2 * 32 + warp] = (unsigned short)__popc(mm);
    __syncthreads();
    // per-class warp scan over the 32 warp-counts
    for (int c2 = warp; c2 < NCLS; c2 += 32) {
        unsigned v = wcount[c2 * 32 + lane];
        unsigned x = v;
        #pragma unroll
        for (int o = 1; o < 32; o <<= 1) {
            unsigned y = __shfl_up_sync(0xffffffffu, x, o);
            if (lane >= o) x += y;
        }
        wbase[c2 * 32 + lane] = (unsigned short)(x - v);
        if (lane == 31) ctot[c2] = (unsigned short)x;
    }
    __syncthreads();
    // class-start prefix by warp 0 (80 = 32+32+16)
    if (warp == 0) {
        unsigned a0 = ctot[lane];
        unsigned a1 = ctot[lane + 32];
        unsigned a2 = (lane + 64 < NCLS) ? ctot[lane + 64] : 0u;
        unsigned s0 = a0, s1 = a1, s2 = a2;
        #pragma unroll
        for (int o = 1; o < 32; o <<= 1) {
            unsigned y0 = __shfl_up_sync(0xffffffffu, s0, o);
            unsigned y1 = __shfl_up_sync(0xffffffffu, s1, o);
            unsigned y2 = __shfl_up_sync(0xffffffffu, s2, o);
            if (lane >= o) { s0 += y0; s1 += y1; s2 += y2; }
        }
        unsigned A0 = __shfl_sync(0xffffffffu, s0, 31);
        unsigned A1 = __shfl_sync(0xffffffffu, s1, 31);
        cstart[lane]      = (unsigned short)(s0 - a0);
        cstart[lane + 32] = (unsigned short)(A0 + s1 - a1);
        if (lane + 64 < NCLS) cstart[lane + 64] = (unsigned short)(A0 + A1 + s2 - a2);
    }
    __syncthreads();
    if (valid) list[cstart[cc2] + wbase[cc2 * 32 + warp] + rank] = (unsigned short)t;
    __syncthreads();

    // ---- per-class greedy (one warp per class, strided) ----
    for (int c2 = warp; c2 < NCLS; c2 += 32) {
        int m = ctot[c2];
        if (m < 2) continue;
        int base = cstart[c2];
        if (m <= 32) {
            int tj = 0; bool kept = false;
            float jy1 = 0, jx1 = 0, jy2 = 0, jx2 = 0, ja = 0;
            if (lane < m) {
                tj = list[base + lane];
                jy1 = sy1[tj]; jx1 = sx1[tj]; jy2 = sy2[tj]; jx2 = sx2[tj]; ja = sa[tj];
                kept = true;
            }
            for (int i = 0; i < m - 1; i++) {
                unsigned alive = __ballot_sync(0xffffffffu, kept);
                if (!((alive >> i) & 1u)) continue;
                int ti = list[base + i];
                float iy1 = sy1[ti], ix1 = sx1[ti], iy2 = sy2[ti], ix2 = sx2[ti], ia = sa[ti];
                if (lane > i && kept) {
                    float yy1 = fmaxf(iy1, jy1);
                    float xx1 = fmaxf(ix1, jx1);
                    float yy2 = fminf(iy2, jy2);
                    float xx2 = fminf(ix2, jx2);
                    float ww = fmaxf(0.0f, __fadd_rn(__fsub_rn(xx2, xx1), 1.0f));
                    float hh = fmaxf(0.0f, __fadd_rn(__fsub_rn(yy2, yy1), 1.0f));
                    float inter = __fmul_rn(ww, hh);
                    float iou = __fdiv_rn(inter, __fsub_rn(__fadd_rn(ia, ja), inter));
                    if (iou > IOUT) kept = false;
                }
            }
            if (lane < m && !kept) atomicAnd(&kw[tj >> 5], ~(1u << (tj & 31)));
        } else {
            for (int i = 0; i < m - 1; i++) {
                __syncwarp();
                if (!skept[base + i]) continue;
                int ti = list[base + i];
                float iy1 = sy1[ti], ix1 = sx1[ti], iy2 = sy2[ti], ix2 = sx2[ti], ia = sa[ti];
                for (int k = i + 1 + lane; k < m; k += 32) {
                    if (skept[base + k]) {
                        int tk = list[base + k];
                        float yy1 = fmaxf(iy1, sy1[tk]);
                        float xx1 = fmaxf(ix1, sx1[tk]);
                        float yy2 = fminf(iy2, sy2[tk]);
                        float xx2 = fminf(ix2, sx2[tk]);
                        float ww = fmaxf(0.0f, __fadd_rn(__fsub_rn(xx2, xx1), 1.0f));
                        float hh = fmaxf(0.0f, __fadd_rn(__fsub_rn(yy2, yy1), 1.0f));
                        float inter = __fmul_rn(ww, hh);
                        float iou = __fdiv_rn(inter, __fsub_rn(__fadd_rn(ia, sa[tk]), inter));
                        if (iou > IOUT) skept[base + k] = 0;
                    }
                }
            }
            __syncwarp();
            for (int k = lane; k < m; k += 32)
                if (!skept[base + k]) {
                    int tk = list[base + k];
                    atomicAnd(&kw[tk >> 5], ~(1u << (tk & 31)));
                }
        }
    }
    __syncthreads();

    // ---- ranking + output ----
    if (t < 32) {
        unsigned my = kw[t];
        int p = __popc(my);
        int x = p;
        #pragma unroll
        for (int o = 1; o < 32; o <<= 1) {
            int y = __shfl_up_sync(0xffffffff, x, o);
            if (t >= o) x += y;
        }
        kpref[t] = x - p;
        if (t == 31) kpref[32] = x;
    }
    __syncthreads();

    int w = t >> 5, l = t & 31;
    unsigned kwv = kw[w];
    bool kept = (kwv >> l) & 1u;
    unsigned lowm = (l == 0) ? 0u : ((1u << l) - 1u);
    int TKall = kpref[32];

    int slot = -1;
    float oscore = 0.0f;
    if (kept) {
        int kr = kpref[w] + __popc(kwv & lowm);
        if (kr < NDET) { slot = kr; oscore = sc; }
    } else {
        int sr = (w << 5) - kpref[w] + __popc((~kwv) & lowm);
        int s2 = TKall + sr;
        if (s2 < NDET) { slot = s2; oscore = 0.0f; }
    }

    // output layout (float32): boxes[32,300,4] | scores[32,300] | labels[32,300] | n_valid[32,1]
    if (slot >= 0) {
        float4 bx = sbox[t];
        float* ob = out + ((size_t)b * NDET + slot) * 4;
        ob[0] = bx.x; ob[1] = bx.y; ob[2] = bx.z; ob[3] = bx.w;
        out[NB * NDET * 4 + b * NDET + slot] = oscore;
        out[NB * NDET * 5 + b * NDET + slot] = (float)c;
    }
    // reset per-replay state
    if (t < 256) g_coarse[b * 256 + t] = 0;
    if (t == 0) {
        out[NB * NDET * 6 + b] = (float)(TKall < NDET ? TKall : NDET);
        g_cnt[b * CSTRIDE] = 0;
        g_cnt[b * CSTRIDE + 1] = 0;
    }
}

// ---------------- launch ----------------------------------------------------
extern "C" void kernel_launch(void* const* d_in, const int* in_sizes, int n_in,
                              void* d_out, int out_size) {
    const float* boxes  = (const float*)d_in[0];
    const float* scores = (const float*)d_in[1];
    if (n_in >= 2 && in_sizes[0] > in_sizes[1]) {
        boxes  = (const float*)d_in[1];
        scores = (const float*)d_in[0];
    }
    float* out = (float*)d_out;

    cudaFuncSetAttribute(k_sortnms, cudaFuncAttributeMaxDynamicSharedMemorySize, CAP * 8);

    k_scan   <<<dim3(HSLICES, NB), 1024>>>((const float4*)scores);
    k_sortnms<<<NB, 1024, CAP * 8>>>((const float4*)boxes, (const float4*)scores, out);
}

// round 13
// speedup vs baseline: 1.5264x; 1.1269x over previous
#include <cuda_runtime.h>
#include <cuda_bf16.h>

// Problem constants
#define NB   32
#define NN   8400
#define NCLS 80
#define NCF  (NN * NCLS)       // 672000 scores per batch
#define TOPK 1024
#define CAP  8192
#define NDET 300
#define THRS 0.001f
#define IOUT 0.7f

#define CLO    0.96875f        // high-region lower bound (31/32, exact fp32)
#define NBINS  32768           // cold-path fine bins
#define HWORDS 16384           // fine bins packed as u16 pairs (64 KB)
#define HSLICES 16
#define SEGCAP 128             // per-warp staging (expected ~41 hits)
#define CAPB   32768           // per-batch candidate buffer (expected ~21000)
#define CSTRIDE 256            // counter spacing (1 KB)

// ---------------- scratch (device globals; no allocation allowed) ----------
__device__ int                 g_cnt[NB * CSTRIDE];       // [b][0]=count, [b][1]=ovf
__device__ unsigned int        g_coarse[NB * 256];        // zero-init; self-reset
__device__ __align__(16) unsigned long long g_cand[NB * CAPB];  // 8 MB

// 21-bit hi-region value: (s-CLO) is exact (Sterbenz), *2^21 exact (pow2).
__device__ __forceinline__ unsigned v21(float s) {
    unsigned v = (unsigned)(__fmul_rn(__fsub_rn(s, CLO), 2097152.0f));
    return v > 65535u ? 65535u : v;
}
__device__ __forceinline__ unsigned binhi(float s)  { return v21(s) >> 8; }   // 0..255
// full-range bin (cold path): 0 for masked scores, else monotonic
__device__ __forceinline__ unsigned binlo2(float s) {
    if (!(s > THRS)) return 0u;
    unsigned b = (unsigned)(s * 32768.0f);
    return b > (NBINS - 1) ? (NBINS - 1) : b;
}

// ---------------- kernel 1: ballot-free scan + coarse hist (unchanged) ------
__global__ void __launch_bounds__(1024) k_scan(const float4* __restrict__ s4) {
    __shared__ unsigned long long stage[32 * SEGCAP];   // 32 KB
    __shared__ unsigned shc[256];
    __shared__ int wctr[32];
    __shared__ int woff[32];
    __shared__ int bbase;
    const int b = blockIdx.y, s = blockIdx.x, t = threadIdx.x;
    const int warp = t >> 5, lane = t & 31;
    if (t < 256) shc[t] = 0;
    if (t < 32) wctr[t] = 0;
    __syncthreads();

    const int perb4 = NCF / 4;                 // 168000
    const int slice = perb4 / HSLICES;         // 10500
    const float4* src = s4 + (size_t)b * perb4 + (size_t)s * slice;
    const unsigned idx0 = (unsigned)((s * slice + t) * 4);
    unsigned long long* mystage = stage + warp * SEGCAP;

    #pragma unroll
    for (int g = 0; g < 10; g++) {
        float4 a = src[g * 1024 + t];
        float mx = fmaxf(fmaxf(a.x, a.y), fmaxf(a.z, a.w));
        if (mx > CLO) {
            float c[4] = {a.x, a.y, a.z, a.w};
            #pragma unroll
            for (int q = 0; q < 4; q++) {
                if (c[q] > CLO) {
                    atomicAdd(&shc[binhi(c[q])], 1u);
                    int p = atomicAdd(&wctr[warp], 1);
                    if (p < SEGCAP)
                        mystage[p] = ((unsigned long long)__float_as_uint(c[q]) << 32)
                                   | (unsigned long long)(~(idx0 + g * 4096u + q));
                }
            }
        }
    }
    if (t < slice - 10240) {
        float4 a = src[10240 + t];
        float mx = fmaxf(fmaxf(a.x, a.y), fmaxf(a.z, a.w));
        if (mx > CLO) {
            float c[4] = {a.x, a.y, a.z, a.w};
            #pragma unroll
            for (int q = 0; q < 4; q++) {
                if (c[q] > CLO) {
                    atomicAdd(&shc[binhi(c[q])], 1u);
                    int p = atomicAdd(&wctr[warp], 1);
                    if (p < SEGCAP)
                        mystage[p] = ((unsigned long long)__float_as_uint(c[q]) << 32)
                                   | (unsigned long long)(~(idx0 + 40960u + q));
                }
            }
        }
    }
    __syncthreads();

    if (t == 0) {
        int run = 0;
        #pragma unroll
        for (int w = 0; w < 32; w++) {
            woff[w] = run;
            int n = wctr[w];
            run += (n > SEGCAP ? SEGCAP : n);
        }
        bbase = atomicAdd(&g_cnt[b * CSTRIDE], run);
    }
    if (t < 32 && wctr[t] > SEGCAP) g_cnt[b * CSTRIDE + 1] = 1;
    __syncthreads();

    int n = wctr[warp]; if (n > SEGCAP) n = SEGCAP;
    unsigned long long* dst = g_cand + (size_t)b * CAPB + bbase + woff[warp];
    for (int off = lane; off < n; off += 32) dst[off] = mystage[off];
    if (t < 256 && shc[t]) atomicAdd(&g_coarse[b * 256 + t], shc[t]);
}

// bitonic register step: element index i, phase k2, distance j (<32)
__device__ __forceinline__ unsigned long long bstep(
    unsigned long long v, int i, int k2, int j) {
    unsigned long long o = __shfl_xor_sync(0xffffffffu, v, j);
    bool keepmax = (((i & k2) == 0) == ((i & j) == 0));
    unsigned long long mx = v > o ? v : o;
    unsigned long long mn = v > o ? o : v;
    return keepmax ? mx : mn;
}

// one-warp descending sort of cnt (<=128) u64 keys in-place at base[0..cnt)
__device__ __forceinline__ void warp_sort128(unsigned long long* base, int cnt, int lane) {
    unsigned long long v[4];
    #pragma unroll
    for (int r = 0; r < 4; r++) {
        int e = r * 32 + lane;
        v[r] = (e < cnt) ? base[e] : 0ull;
    }
    #pragma unroll
    for (int k2 = 2; k2 <= 128; k2 <<= 1) {
        #pragma unroll
        for (int j = 64; j >= 32; j >>= 1) {
            if (j < k2) {
                int jr = j >> 5;
                #pragma unroll
                for (int r = 0; r < 4; r++) {
                    if ((r & jr) == 0) {
                        int pr = r | jr;
                        int e = r * 32 + lane;
                        bool desc = ((e & k2) == 0);
                        unsigned long long lo = v[r], hi = v[pr];
                        unsigned long long mx = lo > hi ? lo : hi;
                        unsigned long long mn = lo > hi ? hi : lo;
                        v[r]  = desc ? mx : mn;
                        v[pr] = desc ? mn : mx;
                    }
                }
            }
        }
        #pragma unroll
        for (int j = 16; j >= 1; j >>= 1) {
            if (j <= (k2 >> 1)) {
                #pragma unroll
                for (int r = 0; r < 4; r++)
                    v[r] = bstep(v[r], r * 32 + lane, k2, j);
            }
        }
    }
    #pragma unroll
    for (int r = 0; r < 4; r++) {
        int e = r * 32 + lane;
        if (e < cnt) base[e] = v[r];
    }
}

// ---------------- kernel 2: bucket-select + warp sorts + NMS + output -------
// key u64 = (float_bits << 32) | ~flat_idx, descending ->
// score desc, flat idx ascending on ties (matches lax.top_k stability).
// Cross-class IoU is exactly 0 (class offset gap), so global greedy ==
// independent per-class greedy in global-rank order. IoU ops identical to
// reference: offset coords, strict > 0.7, __f*_rn arithmetic.
__global__ void __launch_bounds__(1024) k_sortnms(const float4* __restrict__ boxes,
                                                  const float4* __restrict__ s4,
                                                  float* __restrict__ out) {
    extern __shared__ unsigned long long sm[];       // CAP u64 = 64 KB dynamic
    __shared__ int scnt, sT, sSuffT, sMaxSeg;
    __shared__ unsigned sstart[256];
    __shared__ unsigned binpos[256];
    __shared__ float4 sbox[TOPK];                    // 16 KB
    __shared__ float sy1[TOPK], sx1[TOPK], sy2[TOPK], sx2[TOPK], sa[TOPK];
    __shared__ float ssc[TOPK];
    __shared__ short scls[TOPK];
    __shared__ unsigned short wcount[NCLS * 32];
    __shared__ unsigned short wbase [NCLS * 32];
    __shared__ unsigned short ctot[NCLS];
    __shared__ unsigned short cstart[NCLS];
    __shared__ unsigned short list[TOPK];
    __shared__ unsigned char  skept[TOPK];
    __shared__ unsigned kw[32];
    __shared__ int kpref[33];

    int b = blockIdx.x;
    int t = threadIdx.x;
    int warp = t >> 5, lane = t & 31;
    const int perb4 = NCF / 4;
    int rawcnt = g_cnt[b * CSTRIDE];
    int ovf    = g_cnt[b * CSTRIDE + 1];

    if (t == 0) { scnt = 0; sT = 0; sSuffT = 0; sMaxSeg = 0; }
    __syncthreads();

    unsigned long long* cand = g_cand + (size_t)b * CAPB;
    bool hot0 = (rawcnt >= TOPK && rawcnt <= CAPB && !ovf);
    bool fast = false;
    bool hot = false;

    if (hot0) {
        // ---- warp-0: full suffix layout over 256 coarse bins ----
        if (warp == 0) {
            unsigned v[8], s[8];
            #pragma unroll
            for (int k = 0; k < 8; k++) v[k] = g_coarse[b * 256 + lane * 8 + k];
            unsigned run = 0;
            #pragma unroll
            for (int k = 7; k >= 0; k--) { run += v[k]; s[k] = run; }
            unsigned acc = run;
            #pragma unroll
            for (int off = 1; off < 32; off <<= 1) {
                unsigned y = __shfl_down_sync(0xffffffffu, acc, off);
                if (lane + off < 32) acc += y;
            }
            unsigned above = acc - run;
            int bestK = -1;
            #pragma unroll
            for (int k = 0; k < 8; k++) if (s[k] + above >= TOPK) bestK = k;
            unsigned m = __ballot_sync(0xffffffffu, bestK >= 0);
            int selLane = 31 - __clz((int)m);
            unsigned mySuf = (bestK >= 0) ? s[bestK] + above : 0u;
            int selK = __shfl_sync(0xffffffffu, bestK, selLane);
            int T = (selLane << 3) + selK;
            unsigned sufT = __shfl_sync(0xffffffffu, mySuf, selLane);
            // write start offsets for all bins; max segment among bins >= T
            unsigned mx = 0;
            #pragma unroll
            for (int k = 0; k < 8; k++) {
                int bin = lane * 8 + k;
                sstart[bin] = (s[k] + above) - v[k];
                if (bin >= T && v[k] > mx) mx = v[k];
            }
            #pragma unroll
            for (int off = 16; off >= 1; off >>= 1)
                mx = max(mx, __shfl_xor_sync(0xffffffffu, mx, off));
            if (lane == 0) { sT = T; sSuffT = (int)sufT; sMaxSeg = (int)mx; }
        }
        __syncthreads();
        const int T = sT;
        const int suffT = sSuffT;
        hot = (suffT <= CAP);
        if (hot) {
            if (t < 256) binpos[t] = sstart[t];
            __syncthreads();
            // ---- scatter pass: bin >= T -> exact segment position ----
            #pragma unroll 8
            for (int i = t; i < rawcnt; i += 1024) {
                unsigned long long k = cand[i];
                int bi = (int)binhi(__uint_as_float((unsigned)(k >> 32)));
                if (bi >= T) {
                    int p = atomicAdd(&binpos[bi], 1u);
                    sm[p] = k;
                }
            }
            __syncthreads();
            if (sMaxSeg <= 128) {
                // ---- independent per-warp register sorts ----
                for (int bin = 255 - warp; bin >= T; bin -= 32) {
                    int cnt = (int)(binpos[bin] - sstart[bin]);
                    warp_sort128(sm + sstart[bin], cnt, lane);
                }
                fast = true;
                __syncthreads();
            } else {
                // generic bitonic over scattered contiguous [0, suffT)
                int n2 = 2048;
                while (n2 < suffT) n2 <<= 1;
                for (int i = t; i < n2; i += 1024) if (i >= suffT) sm[i] = 0ull;
                __syncthreads();
                for (int k2 = 2; k2 <= n2; k2 <<= 1) {
                    for (int j = k2 >> 1; j > 0; j >>= 1) {
                        for (int i = t; i < n2; i += 1024) {
                            int ixj = i ^ j;
                            if (ixj > i) {
                                unsigned long long x = sm[i], y = sm[ixj];
                                bool desc = ((i & k2) == 0);
                                if (desc ? (x < y) : (x > y)) { sm[i] = y; sm[ixj] = x; }
                            }
                        }
                        __syncthreads();
                    }
                }
            }
        }
    }

    if (!hot) {
        // ---- cold: full-range fine histogram + collect (always correct) ----
        unsigned* sh = (unsigned*)sm;                // 64 KB = HWORDS u32
        for (int i = t; i < HWORDS; i += 1024) sh[i] = 0;
        __syncthreads();
        const float4* src = s4 + (size_t)b * perb4;
        for (int i = t; i < perb4; i += 1024) {
            float4 v = src[i];
            float comp[4] = {v.x, v.y, v.z, v.w};
            #pragma unroll
            for (int q = 0; q < 4; q++) {
                unsigned k = binlo2(comp[q]);
                atomicAdd(&sh[k >> 1], 1u << ((k & 1) * 16));
            }
        }
        __syncthreads();
        if (t < 256) {
            unsigned sum = 0;
            for (int k = 0; k < 64; k++) {
                unsigned m = sh[t * 64 + k];
                sum += (m & 0xFFFFu) + (m >> 16);
            }
            sstart[t] = sum;
        }
        __syncthreads();
        if (t == 0) {
            unsigned h0 = sh[0] & 0xFFFFu;
            int sel = -1; unsigned cum = 0, cums = 0;
            for (int c = 255; c >= 0; c--) {
                unsigned cc = sstart[c] - (c == 0 ? h0 : 0u);
                if (cum + cc >= TOPK) { sel = c; cums = cum; break; }
                cum += cc;
            }
            int T = 1;
            if (sel >= 0) {
                unsigned cum2 = cums;
                int lo = (sel == 0) ? 1 : 0;
                for (int fb = 127; fb >= lo; fb--) {
                    int bin = (sel << 7) + fb;
                    unsigned m = sh[bin >> 1];
                    unsigned cc = (bin & 1) ? (m >> 16) : (m & 0xFFFFu);
                    cum2 += cc;
                    if (cum2 >= TOPK) { T = bin; break; }
                }
            }
            sT = T;
        }
        __syncthreads();
        unsigned T = (unsigned)sT;
        for (int i = t; i < perb4; i += 1024) {
            float4 v = src[i];
            float comp[4] = {v.x, v.y, v.z, v.w};
            #pragma unroll
            for (int q = 0; q < 4; q++) {
                float sv = comp[q];
                if (binlo2(sv) >= T) {
                    int p = atomicAdd(&scnt, 1);
                    if (p < CAPB) {
                        unsigned idx = (unsigned)(i * 4 + q);
                        cand[p] = ((unsigned long long)__float_as_uint(sv) << 32)
                                | (unsigned long long)(~idx);
                    }
                }
            }
        }
        __syncthreads();
        int cc = scnt; if (cc > CAP) cc = CAP;
        for (int i = t; i < cc; i += 1024) sm[i] = cand[i];
        __syncthreads();
        int n2 = 2048;
        while (n2 < cc) n2 <<= 1;
        for (int i = t; i < n2; i += 1024) if (i >= cc) sm[i] = 0ull;
        __syncthreads();
        for (int k2 = 2; k2 <= n2; k2 <<= 1) {
            for (int j = k2 >> 1; j > 0; j >>= 1) {
                for (int i = t; i < n2; i += 1024) {
                    int ixj = i ^ j;
                    if (ixj > i) {
                        unsigned long long x = sm[i], y = sm[ixj];
                        bool desc = ((i & k2) == 0);
                        if (desc ? (x < y) : (x > y)) { sm[i] = y; sm[ixj] = x; }
                    }
                }
                __syncthreads();
            }
        }
    }

    // ---- gather top-1024 boxes + build offset coords ----
    {
        unsigned long long kk = sm[t];
        unsigned keyhi = (unsigned)(kk >> 32);
        float4 bx = make_float4(0.f, 0.f, 0.f, 0.f);
        int cls = 0; float sc = 0.f;
        if (keyhi != 0) {
            unsigned idx = ~(unsigned)(kk & 0xFFFFFFFFull);
            int n = (int)(idx / NCLS);
            cls = (int)(idx % NCLS);
            sc = __uint_as_float(keyhi);
            bx = boxes[b * NN + n];
        }
        sbox[t] = bx; scls[t] = (short)cls; ssc[t] = sc;
        float off = (float)cls * 4096.0f;            // exact in fp32
        float y1 = __fadd_rn(bx.x, off);
        float x1 = __fadd_rn(bx.y, off);
        float y2 = __fadd_rn(bx.z, off);
        float x2 = __fadd_rn(bx.w, off);
        sy1[t] = y1; sx1[t] = x1; sy2[t] = y2; sx2[t] = x2;
        sa[t] = __fmul_rn(__fadd_rn(__fsub_rn(x2, x1), 1.0f),
                          __fadd_rn(__fsub_rn(y2, y1), 1.0f));
    }
    float sc = ssc[t];
    int c = scls[t];
    bool valid = (sc > THRS);
    unsigned bal = __ballot_sync(0xffffffff, valid);
    if (lane == 0) kw[warp] = bal;
    for (int i = t; i < NCLS * 32; i += 1024) wcount[i] = 0;
    skept[t] = 1;
    __syncthreads();

    // ---- stable per-class list build (parallel scans) ----
    int cc2 = valid ? c : 0x7FFF;
    unsigned mm = __match_any_sync(0xffffffffu, cc2);
    int rank = __popc(mm & ((1u << lane) - 1u));
    int ldr = __ffs(mm) - 1;
    if (valid && lane == ldr) wcount[cc2 * 32 + warp] = (unsigned short)__popc(mm);
    __syncthreads();
    for (int c2 = warp; c2 < NCLS; c2 += 32) {
        unsigned v = wcount[c2 * 32 + lane];
        unsigned x = v;
        #pragma unroll
        for (int o = 1; o < 32; o <<= 1) {
            unsigned y = __shfl_up_sync(0xffffffffu, x, o);
            if (lane >= o) x += y;
        }
        wbase[c2 * 32 + lane] = (unsigned short)(x - v);
        if (lane == 31) ctot[c2] = (unsigned short)x;
    }
    __syncthreads();
    if (warp == 0) {
        unsigned a0 = ctot[lane];
        unsigned a1 = ctot[lane + 32];
        unsigned a2 = (lane + 64 < NCLS) ? ctot[lane + 64] : 0u;
        unsigned s0 = a0, s1 = a1, s2 = a2;
        #pragma unroll
        for (int o = 1; o < 32; o <<= 1) {
            unsigned y0 = __shfl_up_sync(0xffffffffu, s0, o);
            unsigned y1 = __shfl_up_sync(0xffffffffu, s1, o);
            unsigned y2 = __shfl_up_sync(0xffffffffu, s2, o);
            if (lane >= o) { s0 += y0; s1 += y1; s2 += y2; }
        }
        unsigned A0 = __shfl_sync(0xffffffffu, s0, 31);
        unsigned A1 = __shfl_sync(0xffffffffu, s1, 31);
        cstart[lane]      = (unsigned short)(s0 - a0);
        cstart[lane + 32] = (unsigned short)(A0 + s1 - a1);
        if (lane + 64 < NCLS) cstart[lane + 64] = (unsigned short)(A0 + A1 + s2 - a2);
    }
    __syncthreads();
    if (valid) list[cstart[cc2] + wbase[cc2 * 32 + warp] + rank] = (unsigned short)t;
    __syncthreads();

    // ---- per-class greedy (one warp per class; two-phase shfl) ----
    for (int c2 = warp; c2 < NCLS; c2 += 32) {
        int m = ctot[c2];
        if (m < 2) continue;
        int base = cstart[c2];
        if (m <= 32) {
            int tj = 0;
            float jy1 = 0, jx1 = 0, jy2 = 0, jx2 = 0, ja = 0;
            bool inr = (lane < m);
            if (inr) {
                tj = list[base + lane];
                jy1 = sy1[tj]; jx1 = sx1[tj]; jy2 = sy2[tj]; jx2 = sx2[tj]; ja = sa[tj];
            }
            // phase 1: pessimistic suppressor masks (independent iterations)
            unsigned sup = 0;
            for (int i = 0; i < m - 1; i++) {
                float iy1 = __shfl_sync(0xffffffffu, jy1, i);
                float ix1 = __shfl_sync(0xffffffffu, jx1, i);
                float iy2 = __shfl_sync(0xffffffffu, jy2, i);
                float ix2 = __shfl_sync(0xffffffffu, jx2, i);
                float ia  = __shfl_sync(0xffffffffu, ja,  i);
                if (lane > i) {
                    float yy1 = fmaxf(iy1, jy1);
                    float xx1 = fmaxf(ix1, jx1);
                    float yy2 = fminf(iy2, jy2);
                    float xx2 = fminf(ix2, jx2);
                    float ww = fmaxf(0.0f, __fadd_rn(__fsub_rn(xx2, xx1), 1.0f));
                    float hh = fmaxf(0.0f, __fadd_rn(__fsub_rn(yy2, yy1), 1.0f));
                    float inter = __fmul_rn(ww, hh);
                    float iou = __fdiv_rn(inter, __fsub_rn(__fadd_rn(ia, ja), inter));
                    if (iou > IOUT) sup |= (1u << i);
                }
            }
            // phase 2: exact greedy resolve (rare)
            unsigned anysup = __ballot_sync(0xffffffffu, inr && sup != 0u);
            bool kept = inr;
            if (anysup) {
                unsigned keptmask = 0;
                for (int i = 0; i < m; i++) {
                    unsigned si = __shfl_sync(0xffffffffu, sup, i);
                    unsigned bit = ((si & keptmask) == 0u) ? 1u : 0u;
                    keptmask |= bit << i;
                }
                kept = inr && ((keptmask >> lane) & 1u);
            }
            if (inr && !kept) atomicAnd(&kw[tj >> 5], ~(1u << (tj & 31)));
        } else {
            for (int i = 0; i < m - 1; i++) {
                __syncwarp();
                if (!skept[base + i]) continue;
                int ti = list[base + i];
                float iy1 = sy1[ti], ix1 = sx1[ti], iy2 = sy2[ti], ix2 = sx2[ti], ia = sa[ti];
                for (int k = i + 1 + lane; k < m; k += 32) {
                    if (skept[base + k]) {
                        int tk = list[base + k];
                        float yy1 = fmaxf(iy1, sy1[tk]);
                        float xx1 = fmaxf(ix1, sx1[tk]);
                        float yy2 = fminf(iy2, sy2[tk]);
                        float xx2 = fminf(ix2, sx2[tk]);
                        float ww = fmaxf(0.0f, __fadd_rn(__fsub_rn(xx2, xx1), 1.0f));
                        float hh = fmaxf(0.0f, __fadd_rn(__fsub_rn(yy2, yy1), 1.0f));
                        float inter = __fmul_rn(ww, hh);
                        float iou = __fdiv_rn(inter, __fsub_rn(__fadd_rn(ia, sa[tk]), inter));
                        if (iou > IOUT) skept[base + k] = 0;
                    }
                }
            }
            __syncwarp();
            for (int k = lane; k < m; k += 32)
                if (!skept[base + k]) {
                    int tk = list[base + k];
                    atomicAnd(&kw[tk >> 5], ~(1u << (tk & 31)));
                }
        }
    }
    __syncthreads();

    // ---- ranking + output ----
    if (t < 32) {
        unsigned my = kw[t];
        int p = __popc(my);
        int x = p;
        #pragma unroll
        for (int o = 1; o < 32; o <<= 1) {
            int y = __shfl_up_sync(0xffffffff, x, o);
            if (t >= o) x += y;
        }
        kpref[t] = x - p;
        if (t == 31) kpref[32] = x;
    }
    __syncthreads();

    int w = t >> 5, l = t & 31;
    unsigned kwv = kw[w];
    bool kept = (kwv >> l) & 1u;
    unsigned lowm = (l == 0) ? 0u : ((1u << l) - 1u);
    int TKall = kpref[32];

    int slot = -1;
    float oscore = 0.0f;
    if (kept) {
        int kr = kpref[w] + __popc(kwv & lowm);
        if (kr < NDET) { slot = kr; oscore = sc; }
    } else {
        int sr = (w << 5) - kpref[w] + __popc((~kwv) & lowm);
        int s2 = TKall + sr;
        if (s2 < NDET) { slot = s2; oscore = 0.0f; }
    }

    // output layout (float32): boxes[32,300,4] | scores[32,300] | labels[32,300] | n_valid[32,1]
    if (slot >= 0) {
        float4 bx = sbox[t];
        float* ob = out + ((size_t)b * NDET + slot) * 4;
        ob[0] = bx.x; ob[1] = bx.y; ob[2] = bx.z; ob[3] = bx.w;
        out[NB * NDET * 4 + b * NDET + slot] = oscore;
        out[NB * NDET * 5 + b * NDET + slot] = (float)c;
    }
    // reset per-replay state
    if (t < 256) g_coarse[b * 256 + t] = 0;
    if (t == 0) {
        out[NB * NDET * 6 + b] = (float)(TKall < NDET ? TKall : NDET);
        g_cnt[b * CSTRIDE] = 0;
        g_cnt[b * CSTRIDE + 1] = 0;
    }
}

// ---------------- launch ----------------------------------------------------
extern "C" void kernel_launch(void* const* d_in, const int* in_sizes, int n_in,
                              void* d_out, int out_size) {
    const float* boxes  = (const float*)d_in[0];
    const float* scores = (const float*)d_in[1];
    if (n_in >= 2 && in_sizes[0] > in_sizes[1]) {
        boxes  = (const float*)d_in[1];
        scores = (const float*)d_in[0];
    }
    float* out = (float*)d_out;

    cudaFuncSetAttribute(k_sortnms, cudaFuncAttributeMaxDynamicSharedMemorySize, CAP * 8);

    k_scan   <<<dim3(HSLICES, NB), 1024>>>((const float4*)scores);
    k_sortnms<<<NB, 1024, CAP * 8>>>((const float4*)boxes, (const float4*)scores, out);
}

// round 14
// speedup vs baseline: 1.5711x; 1.0293x over previous
#include <cuda_runtime.h>
#include <cuda_bf16.h>

// Problem constants
#define NB   32
#define NN   8400
#define NCLS 80
#define NCF  (NN * NCLS)       // 672000 scores per batch
#define TOPK 1024
#define CAP  8192
#define NDET 300
#define THRS 0.001f
#define IOUT 0.7f

#define CLO    0.96875f        // high-region lower bound (31/32, exact fp32)
#define NBINS  32768           // cold-path fine bins
#define HWORDS 16384           // fine bins packed as u16 pairs (64 KB)
#define NB2    1024            // hot-path selection bins (10-bit)
#define HSLICES 16
#define SEGCAP 128             // per-warp staging (expected ~41 hits)
#define CAPB   32768           // per-batch candidate buffer (expected ~21000)
#define CSTRIDE 256            // counter spacing (1 KB)

// ---------------- scratch (device globals; no allocation allowed) ----------
__device__ int                 g_cnt[NB * CSTRIDE];       // [b][0]=count, [b][1]=ovf
__device__ unsigned int        g_coarse[NB * NB2];        // zero-init; self-reset
__device__ __align__(16) unsigned long long g_cand[NB * CAPB];  // 8 MB

// 21-bit hi-region value: (s-CLO) is exact (Sterbenz), *2^21 exact (pow2).
__device__ __forceinline__ unsigned v21(float s) {
    unsigned v = (unsigned)(__fmul_rn(__fsub_rn(s, CLO), 2097152.0f));
    return v > 65535u ? 65535u : v;
}
__device__ __forceinline__ unsigned binhi10(float s) { return v21(s) >> 6; }  // 0..1023
// full-range bin (cold path): 0 for masked scores, else monotonic
__device__ __forceinline__ unsigned binlo2(float s) {
    if (!(s > THRS)) return 0u;
    unsigned b = (unsigned)(s * 32768.0f);
    return b > (NBINS - 1) ? (NBINS - 1) : b;
}

// ---------------- kernel 1: ballot-free scan + fine hist --------------------
__global__ void __launch_bounds__(1024) k_scan(const float4* __restrict__ s4) {
    __shared__ unsigned long long stage[32 * SEGCAP];   // 32 KB
    __shared__ unsigned shc[NB2];                        // 4 KB
    __shared__ int wctr[32];
    __shared__ int woff[32];
    __shared__ int bbase;
    const int b = blockIdx.y, s = blockIdx.x, t = threadIdx.x;
    const int warp = t >> 5, lane = t & 31;
    shc[t] = 0;
    if (t < 32) wctr[t] = 0;
    __syncthreads();

    const int perb4 = NCF / 4;                 // 168000
    const int slice = perb4 / HSLICES;         // 10500
    const float4* src = s4 + (size_t)b * perb4 + (size_t)s * slice;
    const unsigned idx0 = (unsigned)((s * slice + t) * 4);
    unsigned long long* mystage = stage + warp * SEGCAP;

    #pragma unroll
    for (int g = 0; g < 10; g++) {
        float4 a = src[g * 1024 + t];
        float mx = fmaxf(fmaxf(a.x, a.y), fmaxf(a.z, a.w));
        if (mx > CLO) {
            float c[4] = {a.x, a.y, a.z, a.w};
            #pragma unroll
            for (int q = 0; q < 4; q++) {
                if (c[q] > CLO) {
                    atomicAdd(&shc[binhi10(c[q])], 1u);
                    int p = atomicAdd(&wctr[warp], 1);
                    if (p < SEGCAP)
                        mystage[p] = ((unsigned long long)__float_as_uint(c[q]) << 32)
                                   | (unsigned long long)(~(idx0 + g * 4096u + q));
                }
            }
        }
    }
    if (t < slice - 10240) {
        float4 a = src[10240 + t];
        float mx = fmaxf(fmaxf(a.x, a.y), fmaxf(a.z, a.w));
        if (mx > CLO) {
            float c[4] = {a.x, a.y, a.z, a.w};
            #pragma unroll
            for (int q = 0; q < 4; q++) {
                if (c[q] > CLO) {
                    atomicAdd(&shc[binhi10(c[q])], 1u);
                    int p = atomicAdd(&wctr[warp], 1);
                    if (p < SEGCAP)
                        mystage[p] = ((unsigned long long)__float_as_uint(c[q]) << 32)
                                   | (unsigned long long)(~(idx0 + 40960u + q));
                }
            }
        }
    }
    __syncthreads();

    if (t == 0) {
        int run = 0;
        #pragma unroll
        for (int w = 0; w < 32; w++) {
            woff[w] = run;
            int n = wctr[w];
            run += (n > SEGCAP ? SEGCAP : n);
        }
        bbase = atomicAdd(&g_cnt[b * CSTRIDE], run);
    }
    if (t < 32 && wctr[t] > SEGCAP) g_cnt[b * CSTRIDE + 1] = 1;
    __syncthreads();

    int n = wctr[warp]; if (n > SEGCAP) n = SEGCAP;
    unsigned long long* dst = g_cand + (size_t)b * CAPB + bbase + woff[warp];
    for (int off = lane; off < n; off += 32) dst[off] = mystage[off];
    if (shc[t]) atomicAdd(&g_coarse[b * NB2 + t], shc[t]);
}

// bitonic register step: element index i, phase k2, distance j (<32)
__device__ __forceinline__ unsigned long long bstep(
    unsigned long long v, int i, int k2, int j) {
    unsigned long long o = __shfl_xor_sync(0xffffffffu, v, j);
    bool keepmax = (((i & k2) == 0) == ((i & j) == 0));
    unsigned long long mx = v > o ? v : o;
    unsigned long long mn = v > o ? o : v;
    return keepmax ? mx : mn;
}

// one-warp descending sort of cnt (<=32) u64 keys in-place
__device__ __forceinline__ void warp_sort32(unsigned long long* base, int cnt, int lane) {
    unsigned long long v = (lane < cnt) ? base[lane] : 0ull;
    #pragma unroll
    for (int k2 = 2; k2 <= 32; k2 <<= 1)
        #pragma unroll
        for (int j = k2 >> 1; j >= 1; j >>= 1)
            v = bstep(v, lane, k2, j);
    if (lane < cnt) base[lane] = v;
}

// one-warp descending sort of cnt (<=128) u64 keys in-place
__device__ __forceinline__ void warp_sort128(unsigned long long* base, int cnt, int lane) {
    unsigned long long v[4];
    #pragma unroll
    for (int r = 0; r < 4; r++) {
        int e = r * 32 + lane;
        v[r] = (e < cnt) ? base[e] : 0ull;
    }
    #pragma unroll
    for (int k2 = 2; k2 <= 128; k2 <<= 1) {
        #pragma unroll
        for (int j = 64; j >= 32; j >>= 1) {
            if (j < k2) {
                int jr = j >> 5;
                #pragma unroll
                for (int r = 0; r < 4; r++) {
                    if ((r & jr) == 0) {
                        int pr = r | jr;
                        int e = r * 32 + lane;
                        bool desc = ((e & k2) == 0);
                        unsigned long long lo = v[r], hi = v[pr];
                        unsigned long long mx = lo > hi ? lo : hi;
                        unsigned long long mn = lo > hi ? hi : lo;
                        v[r]  = desc ? mx : mn;
                        v[pr] = desc ? mn : mx;
                    }
                }
            }
        }
        #pragma unroll
        for (int j = 16; j >= 1; j >>= 1) {
            if (j <= (k2 >> 1)) {
                #pragma unroll
                for (int r = 0; r < 4; r++)
                    v[r] = bstep(v[r], r * 32 + lane, k2, j);
            }
        }
    }
    #pragma unroll
    for (int r = 0; r < 4; r++) {
        int e = r * 32 + lane;
        if (e < cnt) base[e] = v[r];
    }
}

// ---------------- kernel 2: bucket-select + warp sorts + NMS + output -------
// key u64 = (float_bits << 32) | ~flat_idx, descending ->
// score desc, flat idx ascending on ties (matches lax.top_k stability).
// Cross-class IoU is exactly 0 (class offset gap), so global greedy ==
// independent per-class greedy in global-rank order. IoU ops identical to
// reference: offset coords, strict > 0.7, __f*_rn arithmetic.
__global__ void __launch_bounds__(1024) k_sortnms(const float4* __restrict__ boxes,
                                                  const float4* __restrict__ s4,
                                                  float* __restrict__ out) {
    extern __shared__ unsigned long long sm[];       // CAP u64 = 64 KB dynamic
    __shared__ int scnt, sT, sSuffT, sMaxSeg;
    __shared__ unsigned sstart[NB2];                 // 4 KB
    __shared__ unsigned binpos[NB2];                 // 4 KB
    __shared__ float4 sbox[TOPK];                    // 16 KB
    __shared__ float sy1[TOPK], sx1[TOPK], sy2[TOPK], sx2[TOPK], sa[TOPK];
    __shared__ float ssc[TOPK];
    __shared__ short scls[TOPK];
    __shared__ unsigned short wcount[NCLS * 32];
    __shared__ unsigned short wbase [NCLS * 32];
    __shared__ unsigned short ctot[NCLS];
    __shared__ unsigned short cstart[NCLS];
    __shared__ unsigned short list[TOPK];
    __shared__ unsigned char  skept[TOPK];
    __shared__ unsigned kw[32];
    __shared__ int kpref[33];

    int b = blockIdx.x;
    int t = threadIdx.x;
    int warp = t >> 5, lane = t & 31;
    const int perb4 = NCF / 4;
    int rawcnt = g_cnt[b * CSTRIDE];
    int ovf    = g_cnt[b * CSTRIDE + 1];

    if (t == 0) { scnt = 0; sT = 0; sSuffT = 0; sMaxSeg = 0; }
    sstart[t] = g_coarse[b * NB2 + t];               // counts for layout
    __syncthreads();

    unsigned long long* cand = g_cand + (size_t)b * CAPB;
    bool hot0 = (rawcnt >= TOPK && rawcnt <= CAPB && !ovf);
    bool hot = false;

    if (hot0) {
        // ---- warp-0: in-place suffix layout over 1024 bins ----
        if (warp == 0) {
            // lane owns bins [lane*32, lane*32+32)
            unsigned gsum = 0;
            #pragma unroll
            for (int k = 0; k < 32; k++) gsum += sstart[lane * 32 + k];
            unsigned acc = gsum;
            #pragma unroll
            for (int off = 1; off < 32; off <<= 1) {
                unsigned y = __shfl_down_sync(0xffffffffu, acc, off);
                if (lane + off < 32) acc += y;
            }
            unsigned above = acc - gsum;             // elements in higher groups
            unsigned run = above;
            int localT = -1;
            unsigned localSuff = 0;
            #pragma unroll
            for (int k = 31; k >= 0; k--) {
                int bin = lane * 32 + k;
                unsigned cv = sstart[bin];
                sstart[bin] = run;                   // start offset (suffix layout)
                run += cv;
                if (localT < 0 && run >= TOPK) { localT = bin; localSuff = run; }
            }
            unsigned mb = __ballot_sync(0xffffffffu, localT >= 0);
            int selLane = 31 - __clz((int)mb);
            int T = __shfl_sync(0xffffffffu, localT, selLane);
            unsigned suffT = __shfl_sync(0xffffffffu, (unsigned)localSuff, selLane);
            __syncwarp();
            // max segment among bins >= T (cnt = sstart[bin-1]-sstart[bin])
            unsigned mx = 0;
            for (int bin = T + lane; bin < NB2; bin += 32) {
                unsigned up = (bin == 0) ? (unsigned)rawcnt : sstart[bin - 1];
                unsigned cv = up - sstart[bin];
                if (cv > mx) mx = cv;
            }
            #pragma unroll
            for (int off = 16; off >= 1; off >>= 1)
                mx = max(mx, __shfl_xor_sync(0xffffffffu, mx, off));
            if (lane == 0) { sT = T; sSuffT = (int)suffT; sMaxSeg = (int)mx; }
        }
        __syncthreads();
        const int T = sT;
        const int suffT = sSuffT;
        hot = (suffT <= CAP);
        if (hot) {
            binpos[t] = sstart[t];
            __syncthreads();
            // ---- scatter pass: bin >= T -> exact segment position ----
            #pragma unroll 8
            for (int i = t; i < rawcnt; i += 1024) {
                unsigned long long k = cand[i];
                int bi = (int)binhi10(__uint_as_float((unsigned)(k >> 32)));
                if (bi >= T) {
                    int p = atomicAdd(&binpos[bi], 1u);
                    sm[p] = k;
                }
            }
            __syncthreads();
            if (sMaxSeg <= 128) {
                // ---- independent per-warp sorts (mostly 32-wide) ----
                for (int bin = T + warp; bin < NB2; bin += 32) {
                    int cnt = (int)(binpos[bin] - sstart[bin]);
                    if (cnt > 1) {
                        if (cnt <= 32) warp_sort32(sm + sstart[bin], cnt, lane);
                        else           warp_sort128(sm + sstart[bin], cnt, lane);
                    }
                }
                __syncthreads();
            } else {
                // generic bitonic over scattered contiguous [0, suffT)
                int n2 = 2048;
                while (n2 < suffT) n2 <<= 1;
                for (int i = t; i < n2; i += 1024) if (i >= suffT) sm[i] = 0ull;
                __syncthreads();
                for (int k2 = 2; k2 <= n2; k2 <<= 1) {
                    for (int j = k2 >> 1; j > 0; j >>= 1) {
                        for (int i = t; i < n2; i += 1024) {
                            int ixj = i ^ j;
                            if (ixj > i) {
                                unsigned long long x = sm[i], y = sm[ixj];
                                bool desc = ((i & k2) == 0);
                                if (desc ? (x < y) : (x > y)) { sm[i] = y; sm[ixj] = x; }
                            }
                        }
                        __syncthreads();
                    }
                }
            }
        }
    }

    if (!hot) {
        // ---- cold: full-range fine histogram + collect (always correct) ----
        unsigned* sh = (unsigned*)sm;                // 64 KB = HWORDS u32
        for (int i = t; i < HWORDS; i += 1024) sh[i] = 0;
        __syncthreads();
        const float4* src = s4 + (size_t)b * perb4;
        for (int i = t; i < perb4; i += 1024) {
            float4 v = src[i];
            float comp[4] = {v.x, v.y, v.z, v.w};
            #pragma unroll
            for (int q = 0; q < 4; q++) {
                unsigned k = binlo2(comp[q]);
                atomicAdd(&sh[k >> 1], 1u << ((k & 1) * 16));
            }
        }
        __syncthreads();
        if (t < 256) {
            unsigned sum = 0;
            for (int k = 0; k < 64; k++) {
                unsigned m = sh[t * 64 + k];
                sum += (m & 0xFFFFu) + (m >> 16);
            }
            sstart[t] = sum;
        }
        __syncthreads();
        if (t == 0) {
            unsigned h0 = sh[0] & 0xFFFFu;
            int sel = -1; unsigned cum = 0, cums = 0;
            for (int c = 255; c >= 0; c--) {
                unsigned cc = sstart[c] - (c == 0 ? h0 : 0u);
                if (cum + cc >= TOPK) { sel = c; cums = cum; break; }
                cum += cc;
            }
            int T = 1;
            if (sel >= 0) {
                unsigned cum2 = cums;
                int lo = (sel == 0) ? 1 : 0;
                for (int fb = 127; fb >= lo; fb--) {
                    int bin = (sel << 7) + fb;
                    unsigned m = sh[bin >> 1];
                    unsigned cc = (bin & 1) ? (m >> 16) : (m & 0xFFFFu);
                    cum2 += cc;
                    if (cum2 >= TOPK) { T = bin; break; }
                }
            }
            sT = T;
        }
        __syncthreads();
        unsigned T = (unsigned)sT;
        for (int i = t; i < perb4; i += 1024) {
            float4 v = src[i];
            float comp[4] = {v.x, v.y, v.z, v.w};
            #pragma unroll
            for (int q = 0; q < 4; q++) {
                float sv = comp[q];
                if (binlo2(sv) >= T) {
                    int p = atomicAdd(&scnt, 1);
                    if (p < CAPB) {
                        unsigned idx = (unsigned)(i * 4 + q);
                        cand[p] = ((unsigned long long)__float_as_uint(sv) << 32)
                                | (unsigned long long)(~idx);
                    }
                }
            }
        }
        __syncthreads();
        int cc = scnt; if (cc > CAP) cc = CAP;
        for (int i = t; i < cc; i += 1024) sm[i] = cand[i];
        __syncthreads();
        int n2 = 2048;
        while (n2 < cc) n2 <<= 1;
        for (int i = t; i < n2; i += 1024) if (i >= cc) sm[i] = 0ull;
        __syncthreads();
        for (int k2 = 2; k2 <= n2; k2 <<= 1) {
            for (int j = k2 >> 1; j > 0; j >>= 1) {
                for (int i = t; i < n2; i += 1024) {
                    int ixj = i ^ j;
                    if (ixj > i) {
                        unsigned long long x = sm[i], y = sm[ixj];
                        bool desc = ((i & k2) == 0);
                        if (desc ? (x < y) : (x > y)) { sm[i] = y; sm[ixj] = x; }
                    }
                }
                __syncthreads();
            }
        }
    }

    // ---- gather top-1024 boxes + build offset coords ----
    {
        unsigned long long kk = sm[t];
        unsigned keyhi = (unsigned)(kk >> 32);
        float4 bx = make_float4(0.f, 0.f, 0.f, 0.f);
        int cls = 0; float sc = 0.f;
        if (keyhi != 0) {
            unsigned idx = ~(unsigned)(kk & 0xFFFFFFFFull);
            int n = (int)(idx / NCLS);
            cls = (int)(idx % NCLS);
            sc = __uint_as_float(keyhi);
            bx = boxes[b * NN + n];
        }
        sbox[t] = bx; scls[t] = (short)cls; ssc[t] = sc;
        float off = (float)cls * 4096.0f;            // exact in fp32
        float y1 = __fadd_rn(bx.x, off);
        float x1 = __fadd_rn(bx.y, off);
        float y2 = __fadd_rn(bx.z, off);
        float x2 = __fadd_rn(bx.w, off);
        sy1[t] = y1; sx1[t] = x1; sy2[t] = y2; sx2[t] = x2;
        sa[t] = __fmul_rn(__fadd_rn(__fsub_rn(x2, x1), 1.0f),
                          __fadd_rn(__fsub_rn(y2, y1), 1.0f));
    }
    float sc = ssc[t];
    int c = scls[t];
    bool valid = (sc > THRS);
    unsigned bal = __ballot_sync(0xffffffff, valid);
    if (lane == 0) kw[warp] = bal;
    for (int i = t; i < NCLS * 32; i += 1024) wcount[i] = 0;
    skept[t] = 1;
    __syncthreads();

    // ---- stable per-class list build (parallel scans) ----
    int cc2 = valid ? c : 0x7FFF;
    unsigned mm = __match_any_sync(0xffffffffu, cc2);
    int rank = __popc(mm & ((1u << lane) - 1u));
    int ldr = __ffs(mm) - 1;
    if (valid && lane == ldr) wcount[cc2 * 32 + warp] = (unsigned short)__popc(mm);
    __syncthreads();
    for (int c2 = warp; c2 < NCLS; c2 += 32) {
        unsigned v = wcount[c2 * 32 + lane];
        unsigned x = v;
        #pragma unroll
        for (int o = 1; o < 32; o <<= 1) {
            unsigned y = __shfl_up_sync(0xffffffffu, x, o);
            if (lane >= o) x += y;
        }
        wbase[c2 * 32 + lane] = (unsigned short)(x - v);
        if (lane == 31) ctot[c2] = (unsigned short)x;
    }
    __syncthreads();
    if (warp == 0) {
        unsigned a0 = ctot[lane];
        unsigned a1 = ctot[lane + 32];
        unsigned a2 = (lane + 64 < NCLS) ? ctot[lane + 64] : 0u;
        unsigned s0 = a0, s1 = a1, s2 = a2;
        #pragma unroll
        for (int o = 1; o < 32; o <<= 1) {
            unsigned y0 = __shfl_up_sync(0xffffffffu, s0, o);
            unsigned y1 = __shfl_up_sync(0xffffffffu, s1, o);
            unsigned y2 = __shfl_up_sync(0xffffffffu, s2, o);
            if (lane >= o) { s0 += y0; s1 += y1; s2 += y2; }
        }
        unsigned A0 = __shfl_sync(0xffffffffu, s0, 31);
        unsigned A1 = __shfl_sync(0xffffffffu, s1, 31);
        cstart[lane]      = (unsigned short)(s0 - a0);
        cstart[lane + 32] = (unsigned short)(A0 + s1 - a1);
        if (lane + 64 < NCLS) cstart[lane + 64] = (unsigned short)(A0 + A1 + s2 - a2);
    }
    __syncthreads();
    if (valid) list[cstart[cc2] + wbase[cc2 * 32 + warp] + rank] = (unsigned short)t;
    __syncthreads();

    // ---- per-class greedy (one warp per class; two-phase shfl) ----
    for (int c2 = warp; c2 < NCLS; c2 += 32) {
        int m = ctot[c2];
        if (m < 2) continue;
        int base = cstart[c2];
        if (m <= 32) {
            int tj = 0;
            float jy1 = 0, jx1 = 0, jy2 = 0, jx2 = 0, ja = 0;
            bool inr = (lane < m);
            if (inr) {
                tj = list[base + lane];
                jy1 = sy1[tj]; jx1 = sx1[tj]; jy2 = sy2[tj]; jx2 = sx2[tj]; ja = sa[tj];
            }
            unsigned sup = 0;
            for (int i = 0; i < m - 1; i++) {
                float iy1 = __shfl_sync(0xffffffffu, jy1, i);
                float ix1 = __shfl_sync(0xffffffffu, jx1, i);
                float iy2 = __shfl_sync(0xffffffffu, jy2, i);
                float ix2 = __shfl_sync(0xffffffffu, jx2, i);
                float ia  = __shfl_sync(0xffffffffu, ja,  i);
                if (lane > i) {
                    float yy1 = fmaxf(iy1, jy1);
                    float xx1 = fmaxf(ix1, jx1);
                    float yy2 = fminf(iy2, jy2);
                    float xx2 = fminf(ix2, jx2);
                    float ww = fmaxf(0.0f, __fadd_rn(__fsub_rn(xx2, xx1), 1.0f));
                    float hh = fmaxf(0.0f, __fadd_rn(__fsub_rn(yy2, yy1), 1.0f));
                    float inter = __fmul_rn(ww, hh);
                    float iou = __fdiv_rn(inter, __fsub_rn(__fadd_rn(ia, ja), inter));
                    if (iou > IOUT) sup |= (1u << i);
                }
            }
            unsigned anysup = __ballot_sync(0xffffffffu, inr && sup != 0u);
            bool kept = inr;
            if (anysup) {
                unsigned keptmask = 0;
                for (int i = 0; i < m; i++) {
                    unsigned si = __shfl_sync(0xffffffffu, sup, i);
                    unsigned bit = ((si & keptmask) == 0u) ? 1u : 0u;
                    keptmask |= bit << i;
                }
                kept = inr && ((keptmask >> lane) & 1u);
            }
            if (inr && !kept) atomicAnd(&kw[tj >> 5], ~(1u << (tj & 31)));
        } else {
            for (int i = 0; i < m - 1; i++) {
                __syncwarp();
                if (!skept[base + i]) continue;
                int ti = list[base + i];
                float iy1 = sy1[ti], ix1 = sx1[ti], iy2 = sy2[ti], ix2 = sx2[ti], ia = sa[ti];
                for (int k = i + 1 + lane; k < m; k += 32) {
                    if (skept[base + k]) {
                        int tk = list[base + k];
                        float yy1 = fmaxf(iy1, sy1[tk]);
                        float xx1 = fmaxf(ix1, sx1[tk]);
                        float yy2 = fminf(iy2, sy2[tk]);
                        float xx2 = fminf(ix2, sx2[tk]);
                        float ww = fmaxf(0.0f, __fadd_rn(__fsub_rn(xx2, xx1), 1.0f));
                        float hh = fmaxf(0.0f, __fadd_rn(__fsub_rn(yy2, yy1), 1.0f));
                        float inter = __fmul_rn(ww, hh);
                        float iou = __fdiv_rn(inter, __fsub_rn(__fadd_rn(ia, sa[tk]), inter));
                        if (iou > IOUT) skept[base + k] = 0;
                    }
                }
            }
            __syncwarp();
            for (int k = lane; k < m; k += 32)
                if (!skept[base + k]) {
                    int tk = list[base + k];
                    atomicAnd(&kw[tk >> 5], ~(1u << (tk & 31)));
                }
        }
    }
    __syncthreads();

    // ---- ranking + output ----
    if (t < 32) {
        unsigned my = kw[t];
        int p = __popc(my);
        int x = p;
        #pragma unroll
        for (int o = 1; o < 32; o <<= 1) {
            int y = __shfl_up_sync(0xffffffff, x, o);
            if (t >= o) x += y;
        }
        kpref[t] = x - p;
        if (t == 31) kpref[32] = x;
    }
    __syncthreads();

    int w = t >> 5, l = t & 31;
    unsigned kwv = kw[w];
    bool kept = (kwv >> l) & 1u;
    unsigned lowm = (l == 0) ? 0u : ((1u << l) - 1u);
    int TKall = kpref[32];

    int slot = -1;
    float oscore = 0.0f;
    if (kept) {
        int kr = kpref[w] + __popc(kwv & lowm);
        if (kr < NDET) { slot = kr; oscore = sc; }
    } else {
        int sr = (w << 5) - kpref[w] + __popc((~kwv) & lowm);
        int s2 = TKall + sr;
        if (s2 < NDET) { slot = s2; oscore = 0.0f; }
    }

    // output layout (float32): boxes[32,300,4] | scores[32,300] | labels[32,300] | n_valid[32,1]
    if (slot >= 0) {
        float4 bx = sbox[t];
        float* ob = out + ((size_t)b * NDET + slot) * 4;
        ob[0] = bx.x; ob[1] = bx.y; ob[2] = bx.z; ob[3] = bx.w;
        out[NB * NDET * 4 + b * NDET + slot] = oscore;
        out[NB * NDET * 5 + b * NDET + slot] = (float)c;
    }
    // reset per-replay state
    g_coarse[b * NB2 + t] = 0;
    if (t == 0) {
        out[NB * NDET * 6 + b] = (float)(TKall < NDET ? TKall : NDET);
        g_cnt[b * CSTRIDE] = 0;
        g_cnt[b * CSTRIDE + 1] = 0;
    }
}

// ---------------- launch ----------------------------------------------------
extern "C" void kernel_launch(void* const* d_in, const int* in_sizes, int n_in,
                              void* d_out, int out_size) {
    const float* boxes  = (const float*)d_in[0];
    const float* scores = (const float*)d_in[1];
    if (n_in >= 2 && in_sizes[0] > in_sizes[1]) {
        boxes  = (const float*)d_in[1];
        scores = (const float*)d_in[0];
    }
    float* out = (float*)d_out;

    cudaFuncSetAttribute(k_sortnms, cudaFuncAttributeMaxDynamicSharedMemorySize, CAP * 8);

    k_scan   <<<dim3(HSLICES, NB), 1024>>>((const float4*)scores);
    k_sortnms<<<NB, 1024, CAP * 8>>>((const float4*)boxes, (const float4*)scores, out);
}